// round 2
// baseline (speedup 1.0000x reference)
#include <cuda_runtime.h>
#include <math.h>

#define NB 2
#define NW 8
#define NN 10000
#define NF 5
#define NH 128
#define NBW 16          /* NB*NW */
#define NBN 20000       /* NB*NN */
#define NE_MAX 80000

/* ---------------- scratch (device globals; no allocations allowed) -------- */
__device__ int   d_is64;
__device__ float d_dinv[NN];
__device__ int   d_cnt[NN];
__device__ int   d_rowptr[NN + 1];
__device__ int   d_cursor[NN];
__device__ int   d_colsrc[NE_MAX];
__device__ float d_xagg[NBW * NN * NF];
__device__ float d_h1[NBW * NN * NH];
__device__ float d_h1agg[NBW * NN * NH];
__device__ float d_h2[NBW * NN * NH];
__device__ float d_lstmBT[256 * 512];   /* rows 0..127: W_ih^T, 128..255: W_hh^T */
__device__ float d_bsum[512];
__device__ float d_gtmp[NBN * 512];
__device__ float d_hbuf[NBN * NH];
__device__ float d_cbuf[NBN * NH];

__device__ __forceinline__ float sigf(float x) { return 1.0f / (1.0f + __expf(-x)); }

/* edge_index may be int32 or int64 depending on how the reference was traced.
   Dispatch per-element through a device flag set by k_detect. */
__device__ __forceinline__ int edge_at(const void* ei, int E, int which, int e) {
    if (d_is64) return (int)((const long long*)ei)[(size_t)which * E + e];
    return ((const int*)ei)[(size_t)which * E + e];
}

/* If data is little-endian int64 with values < 2^31, every odd 32-bit word is 0.
   For int32 node ids in [0,10000), odd words are almost surely nonzero somewhere. */
__global__ void k_detect(const int* __restrict__ ei32) {
    if (threadIdx.x == 0) {
        int nz = 0;
        for (int i = 1; i < 2048; i += 2) nz += (ei32[i] != 0);
        d_is64 = (nz == 0) ? 1 : 0;
    }
}

/* ---------------- graph preprocessing ------------------------------------ */
__global__ void k_zero_cnt() {
    int i = blockIdx.x * blockDim.x + threadIdx.x;
    if (i < NN) d_cnt[i] = 0;
}

__global__ void k_count(const void* __restrict__ ei, int E) {
    int e = blockIdx.x * blockDim.x + threadIdx.x;
    if (e < E) {
        int dst = edge_at(ei, E, 1, e);
        if (dst >= 0 && dst < NN) atomicAdd(&d_cnt[dst], 1);
    }
}

/* single-block scan: row_ptr (exclusive), cursor, dinv = rsqrt(indeg+1) */
__global__ void k_scan() {
    __shared__ int ssum[1024];
    const int IPT = 10;   /* 1024*10 >= 10000 */
    int t = threadIdx.x;
    int base = t * IPT;
    int s = 0;
    for (int j = 0; j < IPT; j++) {
        int idx = base + j;
        if (idx < NN) s += d_cnt[idx];
    }
    ssum[t] = s;
    __syncthreads();
    for (int off = 1; off < 1024; off <<= 1) {
        int v = (t >= off) ? ssum[t - off] : 0;
        __syncthreads();
        ssum[t] += v;
        __syncthreads();
    }
    int run = (t == 0) ? 0 : ssum[t - 1];
    for (int j = 0; j < IPT; j++) {
        int idx = base + j;
        if (idx < NN) {
            d_rowptr[idx] = run;
            d_cursor[idx] = run;
            int c = d_cnt[idx];
            d_dinv[idx] = rsqrtf((float)(c + 1));
            run += c;
        }
    }
    if (t == 0) d_rowptr[NN] = ssum[1023];
}

__global__ void k_fill(const void* __restrict__ ei, int E) {
    int e = blockIdx.x * blockDim.x + threadIdx.x;
    if (e < E) {
        int dst = edge_at(ei, E, 1, e);
        int src = edge_at(ei, E, 0, e);
        if (dst >= 0 && dst < NN && src >= 0 && src < NN) {
            int pos = atomicAdd(&d_cursor[dst], 1);
            d_colsrc[pos] = src;
        }
    }
}

/* ---------------- GCN1: aggregate x (F=5), then x@W1 + b, relu ----------- */
__global__ void k_aggx(const float* __restrict__ x) {
    int idx = blockIdx.x * blockDim.x + threadIdx.x;
    if (idx >= NBW * NN * NF) return;
    int f = idx % NF;
    int r = idx / NF;
    int n = r % NN;
    int bw = r / NN;
    float di = d_dinv[n];
    float acc = x[(bw * NN + n) * NF + f] * di * di;   /* self loop */
    int s0 = d_rowptr[n], s1 = d_rowptr[n + 1];
    for (int e = s0; e < s1; e++) {
        int s = d_colsrc[e];
        acc += x[(bw * NN + s) * NF + f] * d_dinv[s] * di;
    }
    d_xagg[idx] = acc;
}

__global__ void k_gcn1(const float* __restrict__ w1, const float* __restrict__ b1) {
    int idx = blockIdx.x * blockDim.x + threadIdx.x;
    if (idx >= NBW * NN * NH) return;
    int h = idx % NH;
    int r = idx / NH;
    const float* xr = &d_xagg[r * NF];
    float acc = b1[h];
#pragma unroll
    for (int f = 0; f < NF; f++) acc = fmaf(xr[f], w1[f * NH + h], acc);
    d_h1[idx] = fmaxf(acc, 0.0f);
}

/* ---------------- GCN2 aggregation over 128 features (atomic-free) ------- */
__global__ void k_gather128() {
    int r = blockIdx.x;          /* bw*NN + n */
    int h = threadIdx.x;         /* 0..127 */
    int n = r % NN;
    int bwBase = r - n;          /* bw*NN */
    float di = d_dinv[n];
    float acc = d_h1[r * NH + h] * di * di;
    int s0 = d_rowptr[n], s1 = d_rowptr[n + 1];
    for (int e = s0; e < s1; e++) {
        int s = __ldg(&d_colsrc[e]);
        acc += d_h1[(bwBase + s) * NH + h] * __ldg(&d_dinv[s]) * di;
    }
    d_h1agg[r * NH + h] = acc;
}

/* ---------------- GCN2 GEMM: (160000x128)@(128x128)+b2, relu -> d_h2 ----- */
__global__ void k_gcn2_gemm(const float* __restrict__ Bm, const float* __restrict__ bias) {
    const int M = NBW * NN, Nn = NH, K = NH;
    __shared__ float As[16][64];
    __shared__ float Bs[16][64];
    int tx = threadIdx.x & 15, ty = threadIdx.x >> 4;
    int m0 = blockIdx.y * 64, n0 = blockIdx.x * 64;
    float acc[4][4] = {};
    for (int k0 = 0; k0 < K; k0 += 16) {
#pragma unroll
        for (int i = 0; i < 4; i++) {
            int idx = threadIdx.x + i * 256;
            int ar = idx >> 4, ac = idx & 15;
            int m = m0 + ar;
            As[ac][ar] = (m < M) ? d_h1agg[m * K + k0 + ac] : 0.0f;
            int kr = idx >> 6, cc = idx & 63;
            Bs[kr][cc] = Bm[(k0 + kr) * Nn + n0 + cc];
        }
        __syncthreads();
#pragma unroll
        for (int kk = 0; kk < 16; kk++) {
            float4 a = *(const float4*)&As[kk][ty * 4];
            float4 b = *(const float4*)&Bs[kk][tx * 4];
            float av[4] = {a.x, a.y, a.z, a.w};
            float bv[4] = {b.x, b.y, b.z, b.w};
#pragma unroll
            for (int i = 0; i < 4; i++)
#pragma unroll
                for (int j = 0; j < 4; j++) acc[i][j] = fmaf(av[i], bv[j], acc[i][j]);
        }
        __syncthreads();
    }
#pragma unroll
    for (int i = 0; i < 4; i++) {
        int m = m0 + ty * 4 + i;
        if (m < M) {
#pragma unroll
            for (int j = 0; j < 4; j++) {
                int c = n0 + tx * 4 + j;
                float v = acc[i][j] + bias[c];
                d_h2[m * Nn + c] = fmaxf(v, 0.0f);
            }
        }
    }
}

/* ---------------- LSTM weight prep --------------------------------------- */
__global__ void k_prep_lstm(const float* __restrict__ wih, const float* __restrict__ whh) {
    int idx = blockIdx.x * blockDim.x + threadIdx.x;
    if (idx >= 256 * 512) return;
    int k = idx / 512, j = idx % 512;
    d_lstmBT[idx] = (k < 128) ? wih[j * 128 + k] : whh[j * 128 + (k - 128)];
}

__global__ void k_bsum(const float* __restrict__ bih, const float* __restrict__ bhh) {
    int j = blockIdx.x * blockDim.x + threadIdx.x;
    if (j < 512) d_bsum[j] = bih[j] + bhh[j];
}

__global__ void k_zero_hc() {
    int i = blockIdx.x * blockDim.x + threadIdx.x;
    if (i < NBN * NH) { d_hbuf[i] = 0.0f; d_cbuf[i] = 0.0f; }
}

/* ---- LSTM gates GEMM: [h2_t | h_prev] (20000x256) @ BT (256x512) + bsum -- */
__global__ void k_lstm_gemm(int t) {
    const int M = NBN, Nn = 512, K = 256;
    __shared__ float As[16][64];
    __shared__ float Bs[16][64];
    int tx = threadIdx.x & 15, ty = threadIdx.x >> 4;
    int m0 = blockIdx.y * 64, n0 = blockIdx.x * 64;
    float acc[4][4] = {};
    for (int k0 = 0; k0 < K; k0 += 16) {
#pragma unroll
        for (int i = 0; i < 4; i++) {
            int idx = threadIdx.x + i * 256;
            int ar = idx >> 4, ac = idx & 15;
            int m = m0 + ar;
            float v = 0.0f;
            if (m < M) {
                int k = k0 + ac;
                if (k < 128) {
                    int b = m / NN;
                    int n = m - b * NN;
                    v = d_h2[((b * NW + t) * NN + n) * NH + k];
                } else {
                    v = d_hbuf[m * NH + (k - 128)];
                }
            }
            As[ac][ar] = v;
            int kr = idx >> 6, cc = idx & 63;
            Bs[kr][cc] = d_lstmBT[(k0 + kr) * Nn + n0 + cc];
        }
        __syncthreads();
#pragma unroll
        for (int kk = 0; kk < 16; kk++) {
            float4 a = *(const float4*)&As[kk][ty * 4];
            float4 b = *(const float4*)&Bs[kk][tx * 4];
            float av[4] = {a.x, a.y, a.z, a.w};
            float bv[4] = {b.x, b.y, b.z, b.w};
#pragma unroll
            for (int i = 0; i < 4; i++)
#pragma unroll
                for (int j = 0; j < 4; j++) acc[i][j] = fmaf(av[i], bv[j], acc[i][j]);
        }
        __syncthreads();
    }
#pragma unroll
    for (int i = 0; i < 4; i++) {
        int m = m0 + ty * 4 + i;
        if (m < M) {
#pragma unroll
            for (int j = 0; j < 4; j++) {
                int c = n0 + tx * 4 + j;
                d_gtmp[m * Nn + c] = acc[i][j] + d_bsum[c];
            }
        }
    }
}

/* ---------------- LSTM pointwise update ---------------------------------- */
__global__ void k_lstm_point() {
    int idx = blockIdx.x * blockDim.x + threadIdx.x;
    if (idx >= NBN * NH) return;
    int m = idx / NH, h = idx % NH;
    int base = m * 512 + h;
    float gi = d_gtmp[base];
    float gf = d_gtmp[base + 128];
    float gg = d_gtmp[base + 256];
    float go = d_gtmp[base + 384];
    float c = sigf(gf) * d_cbuf[idx] + sigf(gi) * tanhf(gg);
    d_cbuf[idx] = c;
    d_hbuf[idx] = sigf(go) * tanhf(c);
}

/* ---------------- decoder: relu(h@W1+b1) @ W2 + b2 ----------------------- */
__global__ void k_dec(const float* __restrict__ w1, const float* __restrict__ b1,
                      const float* __restrict__ w2, const float* __restrict__ b2,
                      float* __restrict__ out) {
    int m = blockIdx.x;
    int j = threadIdx.x;   /* 0..63 */
    const float* hr = &d_hbuf[m * NH];
    float acc = b1[j];
#pragma unroll 8
    for (int k = 0; k < NH; k++) acc = fmaf(hr[k], w1[k * 64 + j], acc);
    __shared__ float red[64];
    red[j] = fmaxf(acc, 0.0f) * w2[j];
    __syncthreads();
    for (int off = 32; off > 0; off >>= 1) {
        if (j < off) red[j] += red[j + off];
        __syncthreads();
    }
    if (j == 0) out[m] = red[0] + b2[0];
}

/* ---------------- host entry --------------------------------------------- */
extern "C" void kernel_launch(void* const* d_in, const int* in_sizes, int n_in,
                              void* d_out, int out_size) {
    const float* x    = (const float*)d_in[0];
    const void*  ei   = d_in[1];
    const float* g1w  = (const float*)d_in[2];
    const float* g1b  = (const float*)d_in[3];
    const float* g2w  = (const float*)d_in[4];
    const float* g2b  = (const float*)d_in[5];
    const float* wih  = (const float*)d_in[6];
    const float* whh  = (const float*)d_in[7];
    const float* bih  = (const float*)d_in[8];
    const float* bhh  = (const float*)d_in[9];
    const float* dw1  = (const float*)d_in[10];
    const float* db1  = (const float*)d_in[11];
    const float* dw2  = (const float*)d_in[12];
    const float* db2  = (const float*)d_in[13];
    float* out = (float*)d_out;
    int E = in_sizes[1] / 2;

    /* graph preprocessing */
    k_detect<<<1, 32>>>((const int*)ei);
    k_zero_cnt<<<(NN + 255) / 256, 256>>>();
    k_count<<<(E + 255) / 256, 256>>>(ei, E);
    k_scan<<<1, 1024>>>();
    k_fill<<<(E + 255) / 256, 256>>>(ei, E);

    /* GCN1 */
    k_aggx<<<(NBW * NN * NF + 255) / 256, 256>>>(x);
    k_gcn1<<<(NBW * NN * NH + 255) / 256, 256>>>(g1w, g1b);

    /* GCN2 */
    k_gather128<<<NBW * NN, 128>>>();
    k_gcn2_gemm<<<dim3(NH / 64, (NBW * NN + 63) / 64), 256>>>(g2w, g2b);

    /* LSTM */
    k_prep_lstm<<<(256 * 512 + 255) / 256, 256>>>(wih, whh);
    k_bsum<<<2, 256>>>(bih, bhh);
    k_zero_hc<<<(NBN * NH + 255) / 256, 256>>>();
    for (int t = 0; t < NW; t++) {
        k_lstm_gemm<<<dim3(512 / 64, (NBN + 63) / 64), 256>>>(t);
        k_lstm_point<<<(NBN * NH + 255) / 256, 256>>>();
    }

    /* decoder */
    k_dec<<<NBN, 64>>>(dw1, db1, dw2, db2, out);
}

// round 5
// speedup vs baseline: 1.6666x; 1.6666x over previous
#include <cuda_runtime.h>
#include <math.h>
#include <stdint.h>

#define NB 2
#define NW 8
#define NN 10000
#define NF 5
#define NH 128
#define NBW 16          /* NB*NW */
#define NBN 20000       /* NB*NN */
#define NE_MAX 80000

/* ---------------- scratch (device globals; no allocations allowed) -------- */
__device__ int   d_is64;
__device__ float d_dinv[NN];
__device__ int   d_cnt[NN];
__device__ int   d_rowptr[NN + 1];
__device__ int   d_cursor[NN];
__device__ int   d_colsrc[NE_MAX];
__device__ float d_xagg[NBW * NN * NF];
__device__ float d_h1[NBW * NN * NH];
__device__ float d_h1agg[NBW * NN * NH];
__device__ float d_h2[NBW * NN * NH];
__device__ float d_lstmBT[256 * 512];   /* rows 0..127: W_ih^T, 128..255: W_hh^T */
__device__ float d_bsum[512];
__device__ float d_gtmp[NBN * 512];
__device__ float d_hbuf[NBN * NH];
__device__ float d_cbuf[NBN * NH];

__device__ __forceinline__ float sigf(float x) { return 1.0f / (1.0f + __expf(-x)); }

/* split x into bf16 hi + bf16 lo (residual); pack pairs (x0 -> low half). */
__device__ __forceinline__ void split_pack(float x0, float x1, uint32_t& hp, uint32_t& lp) {
    uint32_t h;
    asm("cvt.rn.bf16x2.f32 %0, %1, %2;" : "=r"(h) : "f"(x1), "f"(x0));
    float h0 = __uint_as_float(h << 16);
    float h1 = __uint_as_float(h & 0xFFFF0000u);
    uint32_t l;
    asm("cvt.rn.bf16x2.f32 %0, %1, %2;" : "=r"(l) : "f"(x1 - h1), "f"(x0 - h0));
    hp = h; lp = l;
}

/* edge_index may be int32 or int64. Dispatch via device flag set by k_detect. */
__device__ __forceinline__ int edge_at(const void* ei, int E, int which, int e) {
    if (d_is64) return (int)((const long long*)ei)[(size_t)which * E + e];
    return ((const int*)ei)[(size_t)which * E + e];
}

__global__ void k_detect(const int* __restrict__ ei32) {
    if (threadIdx.x == 0) {
        int nz = 0;
        for (int i = 1; i < 2048; i += 2) nz += (ei32[i] != 0);
        d_is64 = (nz == 0) ? 1 : 0;
    }
}

/* ---------------- graph preprocessing ------------------------------------ */
__global__ void k_zero_cnt() {
    int i = blockIdx.x * blockDim.x + threadIdx.x;
    if (i < NN) d_cnt[i] = 0;
}

__global__ void k_count(const void* __restrict__ ei, int E) {
    int e = blockIdx.x * blockDim.x + threadIdx.x;
    if (e < E) {
        int dst = edge_at(ei, E, 1, e);
        if (dst >= 0 && dst < NN) atomicAdd(&d_cnt[dst], 1);
    }
}

__global__ void k_scan() {
    __shared__ int ssum[1024];
    const int IPT = 10;
    int t = threadIdx.x;
    int base = t * IPT;
    int s = 0;
    for (int j = 0; j < IPT; j++) {
        int idx = base + j;
        if (idx < NN) s += d_cnt[idx];
    }
    ssum[t] = s;
    __syncthreads();
    for (int off = 1; off < 1024; off <<= 1) {
        int v = (t >= off) ? ssum[t - off] : 0;
        __syncthreads();
        ssum[t] += v;
        __syncthreads();
    }
    int run = (t == 0) ? 0 : ssum[t - 1];
    for (int j = 0; j < IPT; j++) {
        int idx = base + j;
        if (idx < NN) {
            d_rowptr[idx] = run;
            d_cursor[idx] = run;
            int c = d_cnt[idx];
            d_dinv[idx] = rsqrtf((float)(c + 1));
            run += c;
        }
    }
    if (t == 0) d_rowptr[NN] = ssum[1023];
}

__global__ void k_fill(const void* __restrict__ ei, int E) {
    int e = blockIdx.x * blockDim.x + threadIdx.x;
    if (e < E) {
        int dst = edge_at(ei, E, 1, e);
        int src = edge_at(ei, E, 0, e);
        if (dst >= 0 && dst < NN && src >= 0 && src < NN) {
            int pos = atomicAdd(&d_cursor[dst], 1);
            d_colsrc[pos] = src;
        }
    }
}

/* ---------------- GCN1: aggregate x (F=5), then x@W1 + b, relu ----------- */
__global__ void k_aggx(const float* __restrict__ x) {
    int idx = blockIdx.x * blockDim.x + threadIdx.x;
    if (idx >= NBW * NN * NF) return;
    int f = idx % NF;
    int r = idx / NF;
    int n = r % NN;
    int bw = r / NN;
    float di = d_dinv[n];
    float acc = x[(bw * NN + n) * NF + f] * di * di;
    int s0 = d_rowptr[n], s1 = d_rowptr[n + 1];
    for (int e = s0; e < s1; e++) {
        int s = d_colsrc[e];
        acc += x[(bw * NN + s) * NF + f] * d_dinv[s] * di;
    }
    d_xagg[idx] = acc;
}

__global__ void k_gcn1(const float* __restrict__ w1, const float* __restrict__ b1) {
    int idx = blockIdx.x * blockDim.x + threadIdx.x;
    if (idx >= NBW * NN * NH) return;
    int h = idx % NH;
    int r = idx / NH;
    const float* xr = &d_xagg[r * NF];
    float acc = b1[h];
#pragma unroll
    for (int f = 0; f < NF; f++) acc = fmaf(xr[f], w1[f * NH + h], acc);
    d_h1[idx] = fmaxf(acc, 0.0f);
}

/* ---------------- GCN2 aggregation (atomic-free gather) ------------------ */
__global__ void k_gather128() {
    int r = blockIdx.x;
    int h = threadIdx.x;
    int n = r % NN;
    int bwBase = r - n;
    float di = d_dinv[n];
    float acc = d_h1[r * NH + h] * di * di;
    int s0 = d_rowptr[n], s1 = d_rowptr[n + 1];
    for (int e = s0; e < s1; e++) {
        int s = __ldg(&d_colsrc[e]);
        acc += d_h1[(bwBase + s) * NH + h] * __ldg(&d_dinv[s]) * di;
    }
    d_h1agg[r * NH + h] = acc;
}

/* ---------------- bf16-split tensor-core GEMM ----------------------------
   MODE 0: d_h2 = relu(d_h1agg(160000x128) @ Bext(128x128) + biasext)
   MODE 1: d_gtmp = [h2_t | hbuf](20000x256) @ d_lstmBT(256x512) + d_bsum
   B/bias for MODE 1 are __device__ globals referenced IN DEVICE CODE
   (passing them as host-side kernel args reads the host shadow via ATS!).
---------------------------------------------------------------------------- */
template<int MODE>
__global__ __launch_bounds__(256)
void k_gemm_bf16s(int t, const float* __restrict__ Bext, const float* __restrict__ biasext) {
    const int M = MODE ? NBN : (NBW * NN);
    const int N = MODE ? 512 : NH;
    const int K = MODE ? 256 : NH;
    const float* Bg    = MODE ? (const float*)d_lstmBT : Bext;
    const float* biasg = MODE ? (const float*)d_bsum   : biasext;

    /* A pairs: [m 0..127][k2 0..15], stride 20 */
    __shared__ uint32_t sAh[128 * 20];
    __shared__ uint32_t sAl[128 * 20];
    /* B pairs: [k2 0..15][n 0..127], stride 136 */
    __shared__ uint32_t sBh[16 * 136];
    __shared__ uint32_t sBl[16 * 136];

    int tid = threadIdx.x;
    int lane = tid & 31, wid = tid >> 5;
    int wm = wid & 3, wn = wid >> 2;
    int g = lane >> 2, tq = lane & 3;
    int m0 = blockIdx.y * 128, n0 = blockIdx.x * 128;

    float c[2][8][4];
#pragma unroll
    for (int i = 0; i < 2; i++)
#pragma unroll
        for (int j = 0; j < 8; j++)
#pragma unroll
            for (int q = 0; q < 4; q++) c[i][j][q] = 0.0f;

    int arow = tid >> 1;
    int am = m0 + arow;
    const float* arow0 = 0;
    const float* arow1 = 0;
    if (am < M) {
        if (MODE) {
            int b = am / NN, n = am - b * NN;
            arow0 = &d_h2[((size_t)(b * NW + t) * NN + n) * NH];
            arow1 = &d_hbuf[(size_t)am * NH];
        } else {
            arow0 = &d_h1agg[(size_t)am * NH];
        }
    }
    int bk2 = tid >> 4;
    int nb = (tid & 15) * 8;

    for (int k0 = 0; k0 < K; k0 += 32) {
        float4 av[4];
#pragma unroll
        for (int i = 0; i < 4; i++) {
            int gk = k0 + (tid & 1) * 16 + i * 4;
            float4 v = make_float4(0.f, 0.f, 0.f, 0.f);
            if (am < M) {
                const float* p;
                if (MODE) p = (gk < NH) ? (arow0 + gk) : (arow1 + (gk - NH));
                else      p = arow0 + gk;
                v = *(const float4*)p;
            }
            av[i] = v;
        }
        int bk = k0 + 2 * bk2;
        int gn = n0 + nb;
        float4 b0a = *(const float4*)&Bg[(size_t)bk * N + gn];
        float4 b0b = *(const float4*)&Bg[(size_t)bk * N + gn + 4];
        float4 b1a = *(const float4*)&Bg[(size_t)(bk + 1) * N + gn];
        float4 b1b = *(const float4*)&Bg[(size_t)(bk + 1) * N + gn + 4];

        __syncthreads();
        {
            int k2b = (tid & 1) * 8;
#pragma unroll
            for (int i = 0; i < 4; i++) {
                uint32_t hp, lp;
                split_pack(av[i].x, av[i].y, hp, lp);
                sAh[arow * 20 + k2b + i * 2] = hp;
                sAl[arow * 20 + k2b + i * 2] = lp;
                split_pack(av[i].z, av[i].w, hp, lp);
                sAh[arow * 20 + k2b + i * 2 + 1] = hp;
                sAl[arow * 20 + k2b + i * 2 + 1] = lp;
            }
        }
        {
            float e0[8] = {b0a.x, b0a.y, b0a.z, b0a.w, b0b.x, b0b.y, b0b.z, b0b.w};
            float e1[8] = {b1a.x, b1a.y, b1a.z, b1a.w, b1b.x, b1b.y, b1b.z, b1b.w};
#pragma unroll
            for (int j = 0; j < 8; j++) {
                uint32_t hp, lp;
                split_pack(e0[j], e1[j], hp, lp);
                sBh[bk2 * 136 + nb + j] = hp;
                sBl[bk2 * 136 + nb + j] = lp;
            }
        }
        __syncthreads();

#pragma unroll
        for (int s = 0; s < 2; s++) {
            uint32_t ah[2][4], al[2][4], bh[8][2], bl[8][2];
            int kb = s * 8 + tq;
#pragma unroll
            for (int mt = 0; mt < 2; mt++) {
                int r = wm * 32 + mt * 16 + g;
                ah[mt][0] = sAh[r * 20 + kb];
                ah[mt][1] = sAh[(r + 8) * 20 + kb];
                ah[mt][2] = sAh[r * 20 + kb + 4];
                ah[mt][3] = sAh[(r + 8) * 20 + kb + 4];
                al[mt][0] = sAl[r * 20 + kb];
                al[mt][1] = sAl[(r + 8) * 20 + kb];
                al[mt][2] = sAl[r * 20 + kb + 4];
                al[mt][3] = sAl[(r + 8) * 20 + kb + 4];
            }
#pragma unroll
            for (int nt = 0; nt < 8; nt++) {
                int col = wn * 64 + nt * 8 + g;
                bh[nt][0] = sBh[kb * 136 + col];
                bh[nt][1] = sBh[(kb + 4) * 136 + col];
                bl[nt][0] = sBl[kb * 136 + col];
                bl[nt][1] = sBl[(kb + 4) * 136 + col];
            }
#pragma unroll
            for (int mt = 0; mt < 2; mt++)
#pragma unroll
                for (int nt = 0; nt < 8; nt++) {
                    asm volatile(
                        "mma.sync.aligned.m16n8k16.row.col.f32.bf16.bf16.f32 "
                        "{%0,%1,%2,%3}, {%4,%5,%6,%7}, {%8,%9}, {%0,%1,%2,%3};\n"
                        : "+f"(c[mt][nt][0]), "+f"(c[mt][nt][1]),
                          "+f"(c[mt][nt][2]), "+f"(c[mt][nt][3])
                        : "r"(ah[mt][0]), "r"(ah[mt][1]), "r"(ah[mt][2]), "r"(ah[mt][3]),
                          "r"(bh[nt][0]), "r"(bh[nt][1]));
                    asm volatile(
                        "mma.sync.aligned.m16n8k16.row.col.f32.bf16.bf16.f32 "
                        "{%0,%1,%2,%3}, {%4,%5,%6,%7}, {%8,%9}, {%0,%1,%2,%3};\n"
                        : "+f"(c[mt][nt][0]), "+f"(c[mt][nt][1]),
                          "+f"(c[mt][nt][2]), "+f"(c[mt][nt][3])
                        : "r"(ah[mt][0]), "r"(ah[mt][1]), "r"(ah[mt][2]), "r"(ah[mt][3]),
                          "r"(bl[nt][0]), "r"(bl[nt][1]));
                    asm volatile(
                        "mma.sync.aligned.m16n8k16.row.col.f32.bf16.bf16.f32 "
                        "{%0,%1,%2,%3}, {%4,%5,%6,%7}, {%8,%9}, {%0,%1,%2,%3};\n"
                        : "+f"(c[mt][nt][0]), "+f"(c[mt][nt][1]),
                          "+f"(c[mt][nt][2]), "+f"(c[mt][nt][3])
                        : "r"(al[mt][0]), "r"(al[mt][1]), "r"(al[mt][2]), "r"(al[mt][3]),
                          "r"(bh[nt][0]), "r"(bh[nt][1]));
                }
        }
        __syncthreads();
    }

    float* Cg = MODE ? d_gtmp : d_h2;
#pragma unroll
    for (int mt = 0; mt < 2; mt++) {
        int r0 = m0 + wm * 32 + mt * 16 + g;
#pragma unroll
        for (int nt = 0; nt < 8; nt++) {
            int col = n0 + wn * 64 + nt * 8 + tq * 2;
            float bb0 = biasg[col], bb1 = biasg[col + 1];
            if (r0 < M) {
                float v0 = c[mt][nt][0] + bb0, v1 = c[mt][nt][1] + bb1;
                if (!MODE) { v0 = fmaxf(v0, 0.f); v1 = fmaxf(v1, 0.f); }
                *(float2*)&Cg[(size_t)r0 * N + col] = make_float2(v0, v1);
            }
            if (r0 + 8 < M) {
                float v2 = c[mt][nt][2] + bb0, v3 = c[mt][nt][3] + bb1;
                if (!MODE) { v2 = fmaxf(v2, 0.f); v3 = fmaxf(v3, 0.f); }
                *(float2*)&Cg[(size_t)(r0 + 8) * N + col] = make_float2(v2, v3);
            }
        }
    }
}

/* ---------------- LSTM weight prep --------------------------------------- */
__global__ void k_prep_lstm(const float* __restrict__ wih, const float* __restrict__ whh) {
    int idx = blockIdx.x * blockDim.x + threadIdx.x;
    if (idx >= 256 * 512) return;
    int k = idx / 512, j = idx % 512;
    d_lstmBT[idx] = (k < 128) ? wih[j * 128 + k] : whh[j * 128 + (k - 128)];
}

__global__ void k_bsum(const float* __restrict__ bih, const float* __restrict__ bhh) {
    int j = blockIdx.x * blockDim.x + threadIdx.x;
    if (j < 512) d_bsum[j] = bih[j] + bhh[j];
}

__global__ void k_zero_hc() {
    int i = blockIdx.x * blockDim.x + threadIdx.x;
    if (i < NBN * NH) { d_hbuf[i] = 0.0f; d_cbuf[i] = 0.0f; }
}

/* ---------------- LSTM pointwise update ---------------------------------- */
__global__ void k_lstm_point() {
    int idx = blockIdx.x * blockDim.x + threadIdx.x;
    if (idx >= NBN * NH) return;
    int m = idx / NH, h = idx % NH;
    int base = m * 512 + h;
    float gi = d_gtmp[base];
    float gf = d_gtmp[base + 128];
    float gg = d_gtmp[base + 256];
    float go = d_gtmp[base + 384];
    float c = sigf(gf) * d_cbuf[idx] + sigf(gi) * tanhf(gg);
    d_cbuf[idx] = c;
    d_hbuf[idx] = sigf(go) * tanhf(c);
}

/* ---------------- decoder: relu(h@W1+b1) @ W2 + b2 ----------------------- */
__global__ void k_dec(const float* __restrict__ w1, const float* __restrict__ b1,
                      const float* __restrict__ w2, const float* __restrict__ b2,
                      float* __restrict__ out) {
    int m = blockIdx.x;
    int j = threadIdx.x;
    const float* hr = &d_hbuf[m * NH];
    float acc = b1[j];
#pragma unroll 8
    for (int k = 0; k < NH; k++) acc = fmaf(hr[k], w1[k * 64 + j], acc);
    __shared__ float red[64];
    red[j] = fmaxf(acc, 0.0f) * w2[j];
    __syncthreads();
    for (int off = 32; off > 0; off >>= 1) {
        if (j < off) red[j] += red[j + off];
        __syncthreads();
    }
    if (j == 0) out[m] = red[0] + b2[0];
}

/* ---------------- host entry --------------------------------------------- */
extern "C" void kernel_launch(void* const* d_in, const int* in_sizes, int n_in,
                              void* d_out, int out_size) {
    const float* x    = (const float*)d_in[0];
    const void*  ei   = d_in[1];
    const float* g1w  = (const float*)d_in[2];
    const float* g1b  = (const float*)d_in[3];
    const float* g2w  = (const float*)d_in[4];
    const float* g2b  = (const float*)d_in[5];
    const float* wih  = (const float*)d_in[6];
    const float* whh  = (const float*)d_in[7];
    const float* bih  = (const float*)d_in[8];
    const float* bhh  = (const float*)d_in[9];
    const float* dw1  = (const float*)d_in[10];
    const float* db1  = (const float*)d_in[11];
    const float* dw2  = (const float*)d_in[12];
    const float* db2  = (const float*)d_in[13];
    float* out = (float*)d_out;
    int E = in_sizes[1] / 2;

    /* graph preprocessing */
    k_detect<<<1, 32>>>((const int*)ei);
    k_zero_cnt<<<(NN + 255) / 256, 256>>>();
    k_count<<<(E + 255) / 256, 256>>>(ei, E);
    k_scan<<<1, 1024>>>();
    k_fill<<<(E + 255) / 256, 256>>>(ei, E);

    /* GCN1 */
    k_aggx<<<(NBW * NN * NF + 255) / 256, 256>>>(x);
    k_gcn1<<<(NBW * NN * NH + 255) / 256, 256>>>(g1w, g1b);

    /* GCN2 */
    k_gather128<<<NBW * NN, 128>>>();
    k_gemm_bf16s<0><<<dim3(1, (NBW * NN) / 128), 256>>>(0, g2w, g2b);

    /* LSTM */
    k_prep_lstm<<<(256 * 512 + 255) / 256, 256>>>(wih, whh);
    k_bsum<<<2, 256>>>(bih, bhh);
    k_zero_hc<<<(NBN * NH + 255) / 256, 256>>>();
    for (int t = 0; t < NW; t++) {
        k_gemm_bf16s<1><<<dim3(4, (NBN + 127) / 128), 256>>>(t, (const float*)0, (const float*)0);
        k_lstm_point<<<(NBN * NH + 255) / 256, 256>>>();
    }

    /* decoder */
    k_dec<<<NBN, 64>>>(dw1, db1, dw2, db2, out);
}

// round 6
// speedup vs baseline: 2.4669x; 1.4802x over previous
#include <cuda_runtime.h>
#include <math.h>
#include <stdint.h>

#define NB 2
#define NW 8
#define NN 10000
#define NF 5
#define NH 128
#define NBW 16          /* NB*NW */
#define NBN 20000       /* NB*NN */
#define NE_MAX 80000

/* ---------------- scratch (device globals; no allocations allowed) -------- */
__device__ int   d_is64;
__device__ float d_dinv[NN];
__device__ int   d_cnt[NN];
__device__ int   d_rowptr[NN + 1];
__device__ int   d_cursor[NN];
__device__ int   d_colsrc[NE_MAX];
__device__ float d_xagg[NBW * NN * NF];
__device__ float d_h1[NBW * NN * NH];
/* bf16 hi/lo planes, k-pairs packed in u32 (elem 2j low half, 2j+1 high) */
__device__ uint32_t d_h1h[NBW * NN * 64];   /* gathered layer-2 input */
__device__ uint32_t d_h1l[NBW * NN * 64];
__device__ uint32_t d_h2h[NBW * NN * 64];   /* gcn2 output (lstm input) */
__device__ uint32_t d_h2l[NBW * NN * 64];
__device__ uint32_t d_hbh[NBN * 64];        /* lstm hidden */
__device__ uint32_t d_hbl[NBN * 64];
__device__ uint32_t d_g2h[64 * NH];         /* gcn2 weight planes [k2][n] */
__device__ uint32_t d_g2l[64 * NH];
__device__ uint32_t d_bth[128 * 512];       /* lstm BT planes [k2][n] */
__device__ uint32_t d_btl[128 * 512];
__device__ float d_bsum[512];
__device__ float d_gtmp[NBN * 512];
__device__ float d_hbuf[NBN * NH];
__device__ float d_cbuf[NBN * NH];

__device__ __forceinline__ float sigf(float x) { return 1.0f / (1.0f + __expf(-x)); }

/* split (x0,x1) into bf16 hi pair + bf16 lo (residual) pair; x0 -> low half. */
__device__ __forceinline__ void split_pack(float x0, float x1, uint32_t& hp, uint32_t& lp) {
    uint32_t h;
    asm("cvt.rn.bf16x2.f32 %0, %1, %2;" : "=r"(h) : "f"(x1), "f"(x0));
    float h0 = __uint_as_float(h << 16);
    float h1 = __uint_as_float(h & 0xFFFF0000u);
    uint32_t l;
    asm("cvt.rn.bf16x2.f32 %0, %1, %2;" : "=r"(l) : "f"(x1 - h1), "f"(x0 - h0));
    hp = h; lp = l;
}

__device__ __forceinline__ void cpa16(uint32_t saddr, const void* g) {
    asm volatile("cp.async.cg.shared.global [%0], [%1], 16;\n" :: "r"(saddr), "l"(g));
}

/* edge_index may be int32 or int64. Dispatch via device flag set by k_detect. */
__device__ __forceinline__ int edge_at(const void* ei, int E, int which, int e) {
    if (d_is64) return (int)((const long long*)ei)[(size_t)which * E + e];
    return ((const int*)ei)[(size_t)which * E + e];
}

__global__ void k_detect(const int* __restrict__ ei32) {
    if (threadIdx.x == 0) {
        int nz = 0;
        for (int i = 1; i < 2048; i += 2) nz += (ei32[i] != 0);
        d_is64 = (nz == 0) ? 1 : 0;
    }
}

/* ---------------- graph preprocessing ------------------------------------ */
__global__ void k_zero_cnt() {
    int i = blockIdx.x * blockDim.x + threadIdx.x;
    if (i < NN) d_cnt[i] = 0;
}

__global__ void k_count(const void* __restrict__ ei, int E) {
    int e = blockIdx.x * blockDim.x + threadIdx.x;
    if (e < E) {
        int dst = edge_at(ei, E, 1, e);
        if (dst >= 0 && dst < NN) atomicAdd(&d_cnt[dst], 1);
    }
}

__global__ void k_scan() {
    __shared__ int ssum[1024];
    const int IPT = 10;
    int t = threadIdx.x;
    int base = t * IPT;
    int s = 0;
    for (int j = 0; j < IPT; j++) {
        int idx = base + j;
        if (idx < NN) s += d_cnt[idx];
    }
    ssum[t] = s;
    __syncthreads();
    for (int off = 1; off < 1024; off <<= 1) {
        int v = (t >= off) ? ssum[t - off] : 0;
        __syncthreads();
        ssum[t] += v;
        __syncthreads();
    }
    int run = (t == 0) ? 0 : ssum[t - 1];
    for (int j = 0; j < IPT; j++) {
        int idx = base + j;
        if (idx < NN) {
            d_rowptr[idx] = run;
            d_cursor[idx] = run;
            int c = d_cnt[idx];
            d_dinv[idx] = rsqrtf((float)(c + 1));
            run += c;
        }
    }
    if (t == 0) d_rowptr[NN] = ssum[1023];
}

__global__ void k_fill(const void* __restrict__ ei, int E) {
    int e = blockIdx.x * blockDim.x + threadIdx.x;
    if (e < E) {
        int dst = edge_at(ei, E, 1, e);
        int src = edge_at(ei, E, 0, e);
        if (dst >= 0 && dst < NN && src >= 0 && src < NN) {
            int pos = atomicAdd(&d_cursor[dst], 1);
            d_colsrc[pos] = src;
        }
    }
}

/* ---------------- GCN1: aggregate x (F=5), then x@W1 + b, relu ----------- */
__global__ void k_aggx(const float* __restrict__ x) {
    int idx = blockIdx.x * blockDim.x + threadIdx.x;
    if (idx >= NBW * NN * NF) return;
    int f = idx % NF;
    int r = idx / NF;
    int n = r % NN;
    int bw = r / NN;
    float di = d_dinv[n];
    float acc = x[(bw * NN + n) * NF + f] * di * di;
    int s0 = d_rowptr[n], s1 = d_rowptr[n + 1];
    for (int e = s0; e < s1; e++) {
        int s = d_colsrc[e];
        acc += x[(bw * NN + s) * NF + f] * d_dinv[s] * di;
    }
    d_xagg[idx] = acc;
}

__global__ void k_gcn1(const float* __restrict__ w1, const float* __restrict__ b1) {
    int idx = blockIdx.x * blockDim.x + threadIdx.x;
    if (idx >= NBW * NN * NH) return;
    int h = idx % NH;
    int r = idx / NH;
    const float* xr = &d_xagg[r * NF];
    float acc = b1[h];
#pragma unroll
    for (int f = 0; f < NF; f++) acc = fmaf(xr[f], w1[f * NH + h], acc);
    d_h1[idx] = fmaxf(acc, 0.0f);
}

/* ---------------- GCN2 aggregation -> split planes ----------------------- */
__global__ void k_gather64() {
    int r = blockIdx.x;          /* bw*NN + n */
    int j = threadIdx.x;         /* 0..63 feature pair */
    int n = r % NN;
    int bwBase = r - n;
    float di = d_dinv[n];
    float2 acc = *(const float2*)&d_h1[(size_t)r * NH + 2 * j];
    acc.x *= di * di; acc.y *= di * di;
    int s0 = d_rowptr[n], s1 = d_rowptr[n + 1];
    for (int e = s0; e < s1; e++) {
        int s = __ldg(&d_colsrc[e]);
        float w = __ldg(&d_dinv[s]) * di;
        float2 v = *(const float2*)&d_h1[(size_t)(bwBase + s) * NH + 2 * j];
        acc.x = fmaf(v.x, w, acc.x);
        acc.y = fmaf(v.y, w, acc.y);
    }
    uint32_t hp, lp;
    split_pack(acc.x, acc.y, hp, lp);
    d_h1h[(size_t)r * 64 + j] = hp;
    d_h1l[(size_t)r * 64 + j] = lp;
}

/* ---------------- weight plane prep -------------------------------------- */
__global__ void k_prep_g2w(const float* __restrict__ g2w) {
    int idx = blockIdx.x * blockDim.x + threadIdx.x;
    if (idx >= 64 * NH) return;
    int k2 = idx >> 7, n = idx & 127;
    uint32_t hp, lp;
    split_pack(g2w[(2 * k2) * NH + n], g2w[(2 * k2 + 1) * NH + n], hp, lp);
    d_g2h[idx] = hp; d_g2l[idx] = lp;
}

__global__ void k_prep_lstm(const float* __restrict__ wih, const float* __restrict__ whh) {
    int idx = blockIdx.x * blockDim.x + threadIdx.x;
    if (idx >= 128 * 512) return;
    int k2 = idx >> 9, j = idx & 511;
    float a, b;
    if (k2 < 64) { a = wih[j * 128 + 2 * k2]; b = wih[j * 128 + 2 * k2 + 1]; }
    else         { a = whh[j * 128 + 2 * (k2 - 64)]; b = whh[j * 128 + 2 * (k2 - 64) + 1]; }
    uint32_t hp, lp;
    split_pack(a, b, hp, lp);
    d_bth[idx] = hp; d_btl[idx] = lp;
}

__global__ void k_bsum(const float* __restrict__ bih, const float* __restrict__ bhh) {
    int j = blockIdx.x * blockDim.x + threadIdx.x;
    if (j < 512) d_bsum[j] = bih[j] + bhh[j];
}

__global__ void k_zero_hc() {
    int i = blockIdx.x * blockDim.x + threadIdx.x;
    if (i < NBN * NH) { d_hbuf[i] = 0.0f; d_cbuf[i] = 0.0f; }
    if (i < NBN * 64) { d_hbh[i] = 0u; d_hbl[i] = 0u; }
}

/* ---------------- pipelined bf16-split tensor-core GEMM ------------------
   MODE 0: h2 planes = relu(h1 planes(160000x128) @ g2 planes + g2b)
   MODE 1: d_gtmp = [h2 | hbuf] planes(20000x256) @ bt planes + d_bsum
   256 thr (8 warps 4m x 2n), block tile 128x128, warp tile 32x64, BK=32,
   cp.async double-buffered. All operands pre-split bf16 hi/lo pairs.
---------------------------------------------------------------------------- */
template<int MODE>
__global__ __launch_bounds__(256)
void k_gemm_pipe(int t, const float* __restrict__ biasext) {
    const int M = MODE ? NBN : (NBW * NN);
    const int N = MODE ? 512 : NH;
    const int NIT = MODE ? 8 : 4;
    const float* biasg = MODE ? (const float*)d_bsum : biasext;

    extern __shared__ uint32_t sm[];
    /* buffer layout (u32): Ah 2560 | Al 2560 | Bh 2176 | Bl 2176  = 9472 */

    int tid = threadIdx.x;
    int lane = tid & 31, wid = tid >> 5;
    int wm = wid & 3, wn = wid >> 2;
    int g = lane >> 2, tq = lane & 3;
    int m0 = blockIdx.y * 128, n0 = blockIdx.x * 128;

    float c[2][8][4];
#pragma unroll
    for (int i = 0; i < 2; i++)
#pragma unroll
        for (int j = 0; j < 8; j++)
#pragma unroll
            for (int q = 0; q < 4; q++) c[i][j][q] = 0.0f;

    int arow = tid >> 1, half = tid & 1;
    int am = m0 + arow;
    int amc = am < M ? am : M - 1;
    const uint32_t *Ah0, *Al0, *Ah1 = 0, *Al1 = 0;
    if (MODE) {
        int b = amc / NN, n = amc - b * NN;
        size_t r2 = ((size_t)(b * NW + t) * NN + n) * 64;
        Ah0 = d_h2h + r2; Al0 = d_h2l + r2;
        Ah1 = d_hbh + (size_t)amc * 64; Al1 = d_hbl + (size_t)amc * 64;
    } else {
        Ah0 = d_h1h + (size_t)amc * 64; Al0 = d_h1l + (size_t)amc * 64;
    }
    const uint32_t* Bhp = MODE ? d_bth : d_g2h;
    const uint32_t* Blp = MODE ? d_btl : d_g2l;
    int bk2 = tid >> 4, nb = (tid & 15) * 8;

    uint32_t smbase = (uint32_t)__cvta_generic_to_shared(sm);
    uint32_t sAoff = (arow * 20 + half * 8) * 4;
    uint32_t sBoff = (5120 + bk2 * 136 + nb) * 4;

    auto stage = [&](int buf, int iter) {
        uint32_t sb = smbase + (uint32_t)buf * 9472 * 4;
        int k2b = iter * 16;
        const uint32_t *ah, *al;
        if (MODE && iter >= 4) { ah = Ah1 + (k2b - 64) + half * 8; al = Al1 + (k2b - 64) + half * 8; }
        else                   { ah = Ah0 + k2b + half * 8;        al = Al0 + k2b + half * 8; }
        uint32_t sA = sb + sAoff;
        cpa16(sA, ah);                 cpa16(sA + 16, ah + 4);
        cpa16(sA + 2560 * 4, al);      cpa16(sA + 2560 * 4 + 16, al + 4);
        const uint32_t* bh = Bhp + (size_t)(k2b + bk2) * N + n0 + nb;
        const uint32_t* bl = Blp + (size_t)(k2b + bk2) * N + n0 + nb;
        uint32_t sB = sb + sBoff;
        cpa16(sB, bh);                 cpa16(sB + 16, bh + 4);
        cpa16(sB + 2176 * 4, bl);      cpa16(sB + 2176 * 4 + 16, bl + 4);
        asm volatile("cp.async.commit_group;\n");
    };

    stage(0, 0);
    for (int iter = 0; iter < NIT; iter++) {
        int buf = iter & 1;
        if (iter + 1 < NIT) {
            stage(buf ^ 1, iter + 1);
            asm volatile("cp.async.wait_group 1;\n");
        } else {
            asm volatile("cp.async.wait_group 0;\n");
        }
        __syncthreads();

        const uint32_t* sAh = sm + buf * 9472;
        const uint32_t* sAl = sAh + 2560;
        const uint32_t* sBh = sAh + 5120;
        const uint32_t* sBl = sAh + 7296;

#pragma unroll
        for (int s = 0; s < 2; s++) {
            uint32_t ah[2][4], al[2][4], bh[8][2], bl[8][2];
            int kb = s * 8 + tq;
#pragma unroll
            for (int mt = 0; mt < 2; mt++) {
                int r = wm * 32 + mt * 16 + g;
                ah[mt][0] = sAh[r * 20 + kb];
                ah[mt][1] = sAh[(r + 8) * 20 + kb];
                ah[mt][2] = sAh[r * 20 + kb + 4];
                ah[mt][3] = sAh[(r + 8) * 20 + kb + 4];
                al[mt][0] = sAl[r * 20 + kb];
                al[mt][1] = sAl[(r + 8) * 20 + kb];
                al[mt][2] = sAl[r * 20 + kb + 4];
                al[mt][3] = sAl[(r + 8) * 20 + kb + 4];
            }
#pragma unroll
            for (int nt = 0; nt < 8; nt++) {
                int col = wn * 64 + nt * 8 + g;
                bh[nt][0] = sBh[kb * 136 + col];
                bh[nt][1] = sBh[(kb + 4) * 136 + col];
                bl[nt][0] = sBl[kb * 136 + col];
                bl[nt][1] = sBl[(kb + 4) * 136 + col];
            }
#pragma unroll
            for (int mt = 0; mt < 2; mt++)
#pragma unroll
                for (int nt = 0; nt < 8; nt++) {
                    asm volatile(
                        "mma.sync.aligned.m16n8k16.row.col.f32.bf16.bf16.f32 "
                        "{%0,%1,%2,%3}, {%4,%5,%6,%7}, {%8,%9}, {%0,%1,%2,%3};\n"
                        : "+f"(c[mt][nt][0]), "+f"(c[mt][nt][1]),
                          "+f"(c[mt][nt][2]), "+f"(c[mt][nt][3])
                        : "r"(ah[mt][0]), "r"(ah[mt][1]), "r"(ah[mt][2]), "r"(ah[mt][3]),
                          "r"(bh[nt][0]), "r"(bh[nt][1]));
                    asm volatile(
                        "mma.sync.aligned.m16n8k16.row.col.f32.bf16.bf16.f32 "
                        "{%0,%1,%2,%3}, {%4,%5,%6,%7}, {%8,%9}, {%0,%1,%2,%3};\n"
                        : "+f"(c[mt][nt][0]), "+f"(c[mt][nt][1]),
                          "+f"(c[mt][nt][2]), "+f"(c[mt][nt][3])
                        : "r"(ah[mt][0]), "r"(ah[mt][1]), "r"(ah[mt][2]), "r"(ah[mt][3]),
                          "r"(bl[nt][0]), "r"(bl[nt][1]));
                    asm volatile(
                        "mma.sync.aligned.m16n8k16.row.col.f32.bf16.bf16.f32 "
                        "{%0,%1,%2,%3}, {%4,%5,%6,%7}, {%8,%9}, {%0,%1,%2,%3};\n"
                        : "+f"(c[mt][nt][0]), "+f"(c[mt][nt][1]),
                          "+f"(c[mt][nt][2]), "+f"(c[mt][nt][3])
                        : "r"(al[mt][0]), "r"(al[mt][1]), "r"(al[mt][2]), "r"(al[mt][3]),
                          "r"(bh[nt][0]), "r"(bh[nt][1]));
                }
        }
        __syncthreads();
    }

    /* epilogue */
#pragma unroll
    for (int mt = 0; mt < 2; mt++) {
        int r0 = m0 + wm * 32 + mt * 16 + g;
#pragma unroll
        for (int nt = 0; nt < 8; nt++) {
            int col = n0 + wn * 64 + nt * 8 + tq * 2;
            float bb0 = biasg[col], bb1 = biasg[col + 1];
            if (MODE) {
                if (r0 < M)
                    *(float2*)&d_gtmp[(size_t)r0 * N + col] =
                        make_float2(c[mt][nt][0] + bb0, c[mt][nt][1] + bb1);
                if (r0 + 8 < M)
                    *(float2*)&d_gtmp[(size_t)(r0 + 8) * N + col] =
                        make_float2(c[mt][nt][2] + bb0, c[mt][nt][3] + bb1);
            } else {
                if (r0 < M) {
                    float v0 = fmaxf(c[mt][nt][0] + bb0, 0.f);
                    float v1 = fmaxf(c[mt][nt][1] + bb1, 0.f);
                    uint32_t hp, lp;
                    split_pack(v0, v1, hp, lp);
                    d_h2h[(size_t)r0 * 64 + (col >> 1)] = hp;
                    d_h2l[(size_t)r0 * 64 + (col >> 1)] = lp;
                }
                if (r0 + 8 < M) {
                    float v2 = fmaxf(c[mt][nt][2] + bb0, 0.f);
                    float v3 = fmaxf(c[mt][nt][3] + bb1, 0.f);
                    uint32_t hp, lp;
                    split_pack(v2, v3, hp, lp);
                    d_h2h[(size_t)(r0 + 8) * 64 + (col >> 1)] = hp;
                    d_h2l[(size_t)(r0 + 8) * 64 + (col >> 1)] = lp;
                }
            }
        }
    }
}

/* ---------------- LSTM pointwise update (2 elems/thread) ----------------- */
__global__ void k_lstm_point() {
    int idx = blockIdx.x * blockDim.x + threadIdx.x;
    if (idx >= NBN * 64) return;
    int m = idx >> 6, hp2 = idx & 63;
    int h0 = 2 * hp2;
    int base = m * 512 + h0;
    float gi0 = d_gtmp[base],       gi1 = d_gtmp[base + 1];
    float gf0 = d_gtmp[base + 128], gf1 = d_gtmp[base + 129];
    float gg0 = d_gtmp[base + 256], gg1 = d_gtmp[base + 257];
    float go0 = d_gtmp[base + 384], go1 = d_gtmp[base + 385];
    int ci = m * NH + h0;
    float c0 = sigf(gf0) * d_cbuf[ci]     + sigf(gi0) * tanhf(gg0);
    float c1 = sigf(gf1) * d_cbuf[ci + 1] + sigf(gi1) * tanhf(gg1);
    d_cbuf[ci] = c0; d_cbuf[ci + 1] = c1;
    float hv0 = sigf(go0) * tanhf(c0);
    float hv1 = sigf(go1) * tanhf(c1);
    d_hbuf[ci] = hv0; d_hbuf[ci + 1] = hv1;
    uint32_t hp, lp;
    split_pack(hv0, hv1, hp, lp);
    d_hbh[idx] = hp; d_hbl[idx] = lp;
}

/* ---------------- decoder: relu(h@W1+b1) @ W2 + b2 ----------------------- */
__global__ void k_dec(const float* __restrict__ w1, const float* __restrict__ b1,
                      const float* __restrict__ w2, const float* __restrict__ b2,
                      float* __restrict__ out) {
    int m = blockIdx.x;
    int j = threadIdx.x;
    const float* hr = &d_hbuf[m * NH];
    float acc = b1[j];
#pragma unroll 8
    for (int k = 0; k < NH; k++) acc = fmaf(hr[k], w1[k * 64 + j], acc);
    __shared__ float red[64];
    red[j] = fmaxf(acc, 0.0f) * w2[j];
    __syncthreads();
    for (int off = 32; off > 0; off >>= 1) {
        if (j < off) red[j] += red[j + off];
        __syncthreads();
    }
    if (j == 0) out[m] = red[0] + b2[0];
}

/* ---------------- host entry --------------------------------------------- */
extern "C" void kernel_launch(void* const* d_in, const int* in_sizes, int n_in,
                              void* d_out, int out_size) {
    const float* x    = (const float*)d_in[0];
    const void*  ei   = d_in[1];
    const float* g1w  = (const float*)d_in[2];
    const float* g1b  = (const float*)d_in[3];
    const float* g2w  = (const float*)d_in[4];
    const float* g2b  = (const float*)d_in[5];
    const float* wih  = (const float*)d_in[6];
    const float* whh  = (const float*)d_in[7];
    const float* bih  = (const float*)d_in[8];
    const float* bhh  = (const float*)d_in[9];
    const float* dw1  = (const float*)d_in[10];
    const float* db1  = (const float*)d_in[11];
    const float* dw2  = (const float*)d_in[12];
    const float* db2  = (const float*)d_in[13];
    float* out = (float*)d_out;
    int E = in_sizes[1] / 2;

    const int SMEM = 2 * 9472 * 4;   /* 75776 bytes */
    cudaFuncSetAttribute(k_gemm_pipe<0>, cudaFuncAttributeMaxDynamicSharedMemorySize, SMEM);
    cudaFuncSetAttribute(k_gemm_pipe<1>, cudaFuncAttributeMaxDynamicSharedMemorySize, SMEM);

    /* graph preprocessing */
    k_detect<<<1, 32>>>((const int*)ei);
    k_zero_cnt<<<(NN + 255) / 256, 256>>>();
    k_count<<<(E + 255) / 256, 256>>>(ei, E);
    k_scan<<<1, 1024>>>();
    k_fill<<<(E + 255) / 256, 256>>>(ei, E);

    /* GCN1 */
    k_aggx<<<(NBW * NN * NF + 255) / 256, 256>>>(x);
    k_gcn1<<<(NBW * NN * NH + 255) / 256, 256>>>(g1w, g1b);

    /* GCN2 */
    k_gather64<<<NBW * NN, 64>>>();
    k_prep_g2w<<<(64 * NH + 255) / 256, 256>>>(g2w);
    k_gemm_pipe<0><<<dim3(1, (NBW * NN) / 128), 256, SMEM>>>(0, g2b);

    /* LSTM */
    k_prep_lstm<<<(128 * 512 + 255) / 256, 256>>>(wih, whh);
    k_bsum<<<2, 256>>>(bih, bhh);
    k_zero_hc<<<(NBN * NH + 255) / 256, 256>>>();
    for (int t = 0; t < NW; t++) {
        k_gemm_pipe<1><<<dim3(4, (NBN + 127) / 128), 256, SMEM>>>(t, (const float*)0);
        k_lstm_point<<<(NBN * 64 + 255) / 256, 256>>>();
    }

    /* decoder */
    k_dec<<<NBN, 64>>>(dw1, db1, dw2, db2, out);
}

// round 7
// speedup vs baseline: 2.5795x; 1.0456x over previous
#include <cuda_runtime.h>
#include <math.h>
#include <stdint.h>

#define NB 2
#define NW 8
#define NN 10000
#define NF 5
#define NH 128
#define NBW 16          /* NB*NW */
#define NBN 20000       /* NB*NN */
#define NE_MAX 80000

/* ---------------- scratch (device globals; no allocations allowed) -------- */
__device__ int   d_is64;
__device__ float d_dinv[NN];
__device__ int   d_cnt[NN];
__device__ int   d_rowptr[NN + 1];
__device__ int   d_cursor[NN];
__device__ int   d_colsrc[NE_MAX];
__device__ float d_xagg[NBW * NN * NF];
__device__ float d_h1[NBW * NN * NH];
/* bf16 hi/lo planes, k-pairs packed in u32 (elem 2j low half, 2j+1 high) */
__device__ uint32_t d_h1h[NBW * NN * 64];   /* gathered layer-2 input */
__device__ uint32_t d_h1l[NBW * NN * 64];
__device__ uint32_t d_h2h[NBW * NN * 64];   /* gcn2 output (lstm input) */
__device__ uint32_t d_h2l[NBW * NN * 64];
__device__ uint32_t d_hbh[NBN * 64];        /* lstm hidden */
__device__ uint32_t d_hbl[NBN * 64];
__device__ uint32_t d_g2h[64 * NH];         /* gcn2 weight planes [k2][n] */
__device__ uint32_t d_g2l[64 * NH];
__device__ uint32_t d_bth[128 * 512];       /* lstm BT planes [k2][col'], col'=h*4+gate */
__device__ uint32_t d_btl[128 * 512];
__device__ float d_bsum[512];               /* gate-interleaved bias */
__device__ float d_hbuf[NBN * NH];
__device__ float d_cbuf[NBN * NH];

__device__ __forceinline__ float sigf(float x) { return 1.0f / (1.0f + __expf(-x)); }

/* split (x0,x1) into bf16 hi pair + bf16 lo (residual) pair; x0 -> low half. */
__device__ __forceinline__ void split_pack(float x0, float x1, uint32_t& hp, uint32_t& lp) {
    uint32_t h;
    asm("cvt.rn.bf16x2.f32 %0, %1, %2;" : "=r"(h) : "f"(x1), "f"(x0));
    float h0 = __uint_as_float(h << 16);
    float h1 = __uint_as_float(h & 0xFFFF0000u);
    uint32_t l;
    asm("cvt.rn.bf16x2.f32 %0, %1, %2;" : "=r"(l) : "f"(x1 - h1), "f"(x0 - h0));
    hp = h; lp = l;
}

__device__ __forceinline__ void cpa16(uint32_t saddr, const void* g) {
    asm volatile("cp.async.cg.shared.global [%0], [%1], 16;\n" :: "r"(saddr), "l"(g));
}

/* edge_index may be int32 or int64. Dispatch via device flag set by k_detect. */
__device__ __forceinline__ int edge_at(const void* ei, int E, int which, int e) {
    if (d_is64) return (int)((const long long*)ei)[(size_t)which * E + e];
    return ((const int*)ei)[(size_t)which * E + e];
}

__global__ void k_detect(const int* __restrict__ ei32) {
    int t = threadIdx.x;
    int nz = 0;
    for (int i = 2 * t + 1; i < 4096; i += 512) nz |= ei32[i];
    __shared__ int s;
    if (t == 0) s = 0;
    __syncthreads();
    if (nz) atomicOr(&s, 1);
    __syncthreads();
    if (t == 0) d_is64 = s ? 0 : 1;
}

/* ---------------- graph preprocessing ------------------------------------ */
__global__ void k_zero_cnt() {
    int i = blockIdx.x * blockDim.x + threadIdx.x;
    if (i < NN) d_cnt[i] = 0;
}

__global__ void k_count(const void* __restrict__ ei, int E) {
    int e = blockIdx.x * blockDim.x + threadIdx.x;
    if (e < E) {
        int dst = edge_at(ei, E, 1, e);
        if (dst >= 0 && dst < NN) atomicAdd(&d_cnt[dst], 1);
    }
}

__global__ void k_scan() {
    __shared__ int ssum[1024];
    const int IPT = 10;
    int t = threadIdx.x;
    int base = t * IPT;
    int s = 0;
    for (int j = 0; j < IPT; j++) {
        int idx = base + j;
        if (idx < NN) s += d_cnt[idx];
    }
    ssum[t] = s;
    __syncthreads();
    for (int off = 1; off < 1024; off <<= 1) {
        int v = (t >= off) ? ssum[t - off] : 0;
        __syncthreads();
        ssum[t] += v;
        __syncthreads();
    }
    int run = (t == 0) ? 0 : ssum[t - 1];
    for (int j = 0; j < IPT; j++) {
        int idx = base + j;
        if (idx < NN) {
            d_rowptr[idx] = run;
            d_cursor[idx] = run;
            int c = d_cnt[idx];
            d_dinv[idx] = rsqrtf((float)(c + 1));
            run += c;
        }
    }
    if (t == 0) d_rowptr[NN] = ssum[1023];
}

__global__ void k_fill(const void* __restrict__ ei, int E) {
    int e = blockIdx.x * blockDim.x + threadIdx.x;
    if (e < E) {
        int dst = edge_at(ei, E, 1, e);
        int src = edge_at(ei, E, 0, e);
        if (dst >= 0 && dst < NN && src >= 0 && src < NN) {
            int pos = atomicAdd(&d_cursor[dst], 1);
            d_colsrc[pos] = src;
        }
    }
}

/* ---------------- GCN1: aggregate x (F=5), then x@W1 + b, relu ----------- */
__global__ void k_aggx(const float* __restrict__ x) {
    int idx = blockIdx.x * blockDim.x + threadIdx.x;
    if (idx >= NBW * NN * NF) return;
    int f = idx % NF;
    int r = idx / NF;
    int n = r % NN;
    int bw = r / NN;
    float di = d_dinv[n];
    float acc = x[(bw * NN + n) * NF + f] * di * di;
    int s0 = d_rowptr[n], s1 = d_rowptr[n + 1];
    for (int e = s0; e < s1; e++) {
        int s = d_colsrc[e];
        acc += x[(bw * NN + s) * NF + f] * d_dinv[s] * di;
    }
    d_xagg[idx] = acc;
}

__global__ void k_gcn1(const float* __restrict__ w1, const float* __restrict__ b1) {
    int idx = blockIdx.x * blockDim.x + threadIdx.x;
    if (idx >= NBW * NN * NH) return;
    int h = idx % NH;
    int r = idx / NH;
    const float* xr = &d_xagg[r * NF];
    float acc = b1[h];
#pragma unroll
    for (int f = 0; f < NF; f++) acc = fmaf(xr[f], w1[f * NH + h], acc);
    d_h1[idx] = fmaxf(acc, 0.0f);
}

/* ---------------- GCN2 aggregation -> split planes ----------------------- */
__global__ void k_gather64() {
    int r = blockIdx.x;          /* bw*NN + n */
    int j = threadIdx.x;         /* 0..63 feature pair */
    int n = r % NN;
    int bwBase = r - n;
    float di = d_dinv[n];
    float2 acc = *(const float2*)&d_h1[(size_t)r * NH + 2 * j];
    acc.x *= di * di; acc.y *= di * di;
    int s0 = d_rowptr[n], s1 = d_rowptr[n + 1];
    for (int e = s0; e < s1; e++) {
        int s = __ldg(&d_colsrc[e]);
        float w = __ldg(&d_dinv[s]) * di;
        float2 v = *(const float2*)&d_h1[(size_t)(bwBase + s) * NH + 2 * j];
        acc.x = fmaf(v.x, w, acc.x);
        acc.y = fmaf(v.y, w, acc.y);
    }
    uint32_t hp, lp;
    split_pack(acc.x, acc.y, hp, lp);
    d_h1h[(size_t)r * 64 + j] = hp;
    d_h1l[(size_t)r * 64 + j] = lp;
}

/* ---------------- weight plane prep -------------------------------------- */
__global__ void k_prep_g2w(const float* __restrict__ g2w) {
    int idx = blockIdx.x * blockDim.x + threadIdx.x;
    if (idx >= 64 * NH) return;
    int k2 = idx >> 7, n = idx & 127;
    uint32_t hp, lp;
    split_pack(g2w[(2 * k2) * NH + n], g2w[(2 * k2 + 1) * NH + n], hp, lp);
    d_g2h[idx] = hp; d_g2l[idx] = lp;
}

/* gate-interleaved: col' = h*4 + gate; original row j = gate*128 + h */
__global__ void k_prep_lstm(const float* __restrict__ wih, const float* __restrict__ whh) {
    int idx = blockIdx.x * blockDim.x + threadIdx.x;
    if (idx >= 128 * 512) return;
    int k2 = idx >> 9, col = idx & 511;
    int j = (col & 3) * 128 + (col >> 2);
    float a, b;
    if (k2 < 64) { a = wih[j * 128 + 2 * k2]; b = wih[j * 128 + 2 * k2 + 1]; }
    else         { a = whh[j * 128 + 2 * (k2 - 64)]; b = whh[j * 128 + 2 * (k2 - 64) + 1]; }
    uint32_t hp, lp;
    split_pack(a, b, hp, lp);
    d_bth[idx] = hp; d_btl[idx] = lp;
}

__global__ void k_bsum(const float* __restrict__ bih, const float* __restrict__ bhh) {
    int col = blockIdx.x * blockDim.x + threadIdx.x;
    if (col < 512) {
        int j = (col & 3) * 128 + (col >> 2);
        d_bsum[col] = bih[j] + bhh[j];
    }
}

__global__ void k_zero_hc() {
    int i = blockIdx.x * blockDim.x + threadIdx.x;
    if (i < NBN * NH) { d_hbuf[i] = 0.0f; d_cbuf[i] = 0.0f; }
    if (i < NBN * 64) { d_hbh[i] = 0u; d_hbl[i] = 0u; }
}

/* ---------------- pipelined bf16-split tensor-core GEMM ------------------
   MODE 0: h2 planes = relu(h1 planes(160000x128) @ g2 planes + g2b)
   MODE 1: gates = [h2_t | hbuf](20000x256) @ bt planes + bsum, then the
           FULL LSTM cell update fused in the epilogue (gate-interleaved
           weight layout: a 128-col tile = 4 gates x 32 hidden units).
---------------------------------------------------------------------------- */
template<int MODE>
__global__ __launch_bounds__(256)
void k_gemm_pipe(int t, const float* __restrict__ biasext) {
    const int M = MODE ? NBN : (NBW * NN);
    const int N = MODE ? 512 : NH;
    const int NIT = MODE ? 8 : 4;

    extern __shared__ uint32_t sm[];
    /* buffer layout (u32): Ah 2560 | Al 2560 | Bh 2176 | Bl 2176  = 9472 */

    int tid = threadIdx.x;
    int lane = tid & 31, wid = tid >> 5;
    int wm = wid & 3, wn = wid >> 2;
    int g = lane >> 2, tq = lane & 3;
    int m0 = blockIdx.y * 128, n0 = blockIdx.x * 128;

    float c[2][8][4];
#pragma unroll
    for (int i = 0; i < 2; i++)
#pragma unroll
        for (int j = 0; j < 8; j++)
#pragma unroll
            for (int q = 0; q < 4; q++) c[i][j][q] = 0.0f;

    int arow = tid >> 1, half = tid & 1;
    int am = m0 + arow;
    int amc = am < M ? am : M - 1;
    const uint32_t *Ah0, *Al0, *Ah1 = 0, *Al1 = 0;
    if (MODE) {
        int b = amc / NN, n = amc - b * NN;
        size_t r2 = ((size_t)(b * NW + t) * NN + n) * 64;
        Ah0 = d_h2h + r2; Al0 = d_h2l + r2;
        Ah1 = d_hbh + (size_t)amc * 64; Al1 = d_hbl + (size_t)amc * 64;
    } else {
        Ah0 = d_h1h + (size_t)amc * 64; Al0 = d_h1l + (size_t)amc * 64;
    }
    const uint32_t* Bhp = MODE ? d_bth : d_g2h;
    const uint32_t* Blp = MODE ? d_btl : d_g2l;
    int bk2 = tid >> 4, nb = (tid & 15) * 8;

    uint32_t smbase = (uint32_t)__cvta_generic_to_shared(sm);
    uint32_t sAoff = (arow * 20 + half * 8) * 4;
    uint32_t sBoff = (5120 + bk2 * 136 + nb) * 4;

    auto stage = [&](int buf, int iter) {
        uint32_t sb = smbase + (uint32_t)buf * 9472 * 4;
        int k2b = iter * 16;
        const uint32_t *ah, *al;
        if (MODE && iter >= 4) { ah = Ah1 + (k2b - 64) + half * 8; al = Al1 + (k2b - 64) + half * 8; }
        else                   { ah = Ah0 + k2b + half * 8;        al = Al0 + k2b + half * 8; }
        uint32_t sA = sb + sAoff;
        cpa16(sA, ah);                 cpa16(sA + 16, ah + 4);
        cpa16(sA + 2560 * 4, al);      cpa16(sA + 2560 * 4 + 16, al + 4);
        const uint32_t* bh = Bhp + (size_t)(k2b + bk2) * N + n0 + nb;
        const uint32_t* bl = Blp + (size_t)(k2b + bk2) * N + n0 + nb;
        uint32_t sB = sb + sBoff;
        cpa16(sB, bh);                 cpa16(sB + 16, bh + 4);
        cpa16(sB + 2176 * 4, bl);      cpa16(sB + 2176 * 4 + 16, bl + 4);
        asm volatile("cp.async.commit_group;\n");
    };

    stage(0, 0);
    for (int iter = 0; iter < NIT; iter++) {
        int buf = iter & 1;
        if (iter + 1 < NIT) {
            stage(buf ^ 1, iter + 1);
            asm volatile("cp.async.wait_group 1;\n");
        } else {
            asm volatile("cp.async.wait_group 0;\n");
        }
        __syncthreads();

        const uint32_t* sAh = sm + buf * 9472;
        const uint32_t* sAl = sAh + 2560;
        const uint32_t* sBh = sAh + 5120;
        const uint32_t* sBl = sAh + 7296;

#pragma unroll
        for (int s = 0; s < 2; s++) {
            uint32_t ah[2][4], al[2][4], bh[8][2], bl[8][2];
            int kb = s * 8 + tq;
#pragma unroll
            for (int mt = 0; mt < 2; mt++) {
                int r = wm * 32 + mt * 16 + g;
                ah[mt][0] = sAh[r * 20 + kb];
                ah[mt][1] = sAh[(r + 8) * 20 + kb];
                ah[mt][2] = sAh[r * 20 + kb + 4];
                ah[mt][3] = sAh[(r + 8) * 20 + kb + 4];
                al[mt][0] = sAl[r * 20 + kb];
                al[mt][1] = sAl[(r + 8) * 20 + kb];
                al[mt][2] = sAl[r * 20 + kb + 4];
                al[mt][3] = sAl[(r + 8) * 20 + kb + 4];
            }
#pragma unroll
            for (int nt = 0; nt < 8; nt++) {
                int col = wn * 64 + nt * 8 + g;
                bh[nt][0] = sBh[kb * 136 + col];
                bh[nt][1] = sBh[(kb + 4) * 136 + col];
                bl[nt][0] = sBl[kb * 136 + col];
                bl[nt][1] = sBl[(kb + 4) * 136 + col];
            }
#pragma unroll
            for (int mt = 0; mt < 2; mt++)
#pragma unroll
                for (int nt = 0; nt < 8; nt++) {
                    asm volatile(
                        "mma.sync.aligned.m16n8k16.row.col.f32.bf16.bf16.f32 "
                        "{%0,%1,%2,%3}, {%4,%5,%6,%7}, {%8,%9}, {%0,%1,%2,%3};\n"
                        : "+f"(c[mt][nt][0]), "+f"(c[mt][nt][1]),
                          "+f"(c[mt][nt][2]), "+f"(c[mt][nt][3])
                        : "r"(ah[mt][0]), "r"(ah[mt][1]), "r"(ah[mt][2]), "r"(ah[mt][3]),
                          "r"(bh[nt][0]), "r"(bh[nt][1]));
                    asm volatile(
                        "mma.sync.aligned.m16n8k16.row.col.f32.bf16.bf16.f32 "
                        "{%0,%1,%2,%3}, {%4,%5,%6,%7}, {%8,%9}, {%0,%1,%2,%3};\n"
                        : "+f"(c[mt][nt][0]), "+f"(c[mt][nt][1]),
                          "+f"(c[mt][nt][2]), "+f"(c[mt][nt][3])
                        : "r"(ah[mt][0]), "r"(ah[mt][1]), "r"(ah[mt][2]), "r"(ah[mt][3]),
                          "r"(bl[nt][0]), "r"(bl[nt][1]));
                    asm volatile(
                        "mma.sync.aligned.m16n8k16.row.col.f32.bf16.bf16.f32 "
                        "{%0,%1,%2,%3}, {%4,%5,%6,%7}, {%8,%9}, {%0,%1,%2,%3};\n"
                        : "+f"(c[mt][nt][0]), "+f"(c[mt][nt][1]),
                          "+f"(c[mt][nt][2]), "+f"(c[mt][nt][3])
                        : "r"(al[mt][0]), "r"(al[mt][1]), "r"(al[mt][2]), "r"(al[mt][3]),
                          "r"(bh[nt][0]), "r"(bh[nt][1]));
                }
        }
        __syncthreads();
    }

    if (MODE) {
        /* ---- fused LSTM cell epilogue (reuse pipeline smem) ---- */
        float* sf = (float*)sm;   /* [128 rows][132 cols] fp32 gates */
#pragma unroll
        for (int mt = 0; mt < 2; mt++) {
            int lr = wm * 32 + mt * 16 + g;
#pragma unroll
            for (int nt = 0; nt < 8; nt++) {
                int lc = wn * 64 + nt * 8 + tq * 2;
                float bb0 = d_bsum[n0 + lc], bb1 = d_bsum[n0 + lc + 1];
                *(float2*)&sf[lr * 132 + lc] =
                    make_float2(c[mt][nt][0] + bb0, c[mt][nt][1] + bb1);
                *(float2*)&sf[(lr + 8) * 132 + lc] =
                    make_float2(c[mt][nt][2] + bb0, c[mt][nt][3] + bb1);
            }
        }
        __syncthreads();
        int h0 = blockIdx.x * 32;   /* n0 = 4*h0 */
#pragma unroll
        for (int it = 0; it < 8; it++) {
            int idx = tid + it * 256;      /* 0..2047 */
            int lr = idx >> 4;             /* row 0..127 */
            int hp2 = idx & 15;            /* local h-pair 0..15 */
            int gm = m0 + lr;
            if (gm < M) {
                float4 gA = *(float4*)&sf[lr * 132 + hp2 * 8];      /* i,f,g,o for h even */
                float4 gB = *(float4*)&sf[lr * 132 + hp2 * 8 + 4];  /* i,f,g,o for h odd */
                int hg = h0 + 2 * hp2;
                int ci = gm * NH + hg;
                float2 cp = *(float2*)&d_cbuf[ci];
                float c0n = sigf(gA.y) * cp.x + sigf(gA.x) * tanhf(gA.z);
                float c1n = sigf(gB.y) * cp.y + sigf(gB.x) * tanhf(gB.z);
                float h0n = sigf(gA.w) * tanhf(c0n);
                float h1n = sigf(gB.w) * tanhf(c1n);
                *(float2*)&d_cbuf[ci] = make_float2(c0n, c1n);
                *(float2*)&d_hbuf[ci] = make_float2(h0n, h1n);
                uint32_t hpv, lpv;
                split_pack(h0n, h1n, hpv, lpv);
                d_hbh[(size_t)gm * 64 + (hg >> 1)] = hpv;
                d_hbl[(size_t)gm * 64 + (hg >> 1)] = lpv;
            }
        }
    } else {
        /* ---- GCN2 epilogue: relu + split to h2 planes ---- */
#pragma unroll
        for (int mt = 0; mt < 2; mt++) {
            int r0 = m0 + wm * 32 + mt * 16 + g;
#pragma unroll
            for (int nt = 0; nt < 8; nt++) {
                int col = n0 + wn * 64 + nt * 8 + tq * 2;
                float bb0 = biasext[col], bb1 = biasext[col + 1];
                if (r0 < M) {
                    float v0 = fmaxf(c[mt][nt][0] + bb0, 0.f);
                    float v1 = fmaxf(c[mt][nt][1] + bb1, 0.f);
                    uint32_t hp, lp;
                    split_pack(v0, v1, hp, lp);
                    d_h2h[(size_t)r0 * 64 + (col >> 1)] = hp;
                    d_h2l[(size_t)r0 * 64 + (col >> 1)] = lp;
                }
                if (r0 + 8 < M) {
                    float v2 = fmaxf(c[mt][nt][2] + bb0, 0.f);
                    float v3 = fmaxf(c[mt][nt][3] + bb1, 0.f);
                    uint32_t hp, lp;
                    split_pack(v2, v3, hp, lp);
                    d_h2h[(size_t)(r0 + 8) * 64 + (col >> 1)] = hp;
                    d_h2l[(size_t)(r0 + 8) * 64 + (col >> 1)] = lp;
                }
            }
        }
    }
}

/* ---------------- decoder: relu(h@W1+b1) @ W2 + b2 ----------------------- */
__global__ void k_dec(const float* __restrict__ w1, const float* __restrict__ b1,
                      const float* __restrict__ w2, const float* __restrict__ b2,
                      float* __restrict__ out) {
    int m = blockIdx.x;
    int j = threadIdx.x;
    const float* hr = &d_hbuf[m * NH];
    float acc = b1[j];
#pragma unroll 8
    for (int k = 0; k < NH; k++) acc = fmaf(hr[k], w1[k * 64 + j], acc);
    __shared__ float red[64];
    red[j] = fmaxf(acc, 0.0f) * w2[j];
    __syncthreads();
    for (int off = 32; off > 0; off >>= 1) {
        if (j < off) red[j] += red[j + off];
        __syncthreads();
    }
    if (j == 0) out[m] = red[0] + b2[0];
}

/* ---------------- host entry --------------------------------------------- */
extern "C" void kernel_launch(void* const* d_in, const int* in_sizes, int n_in,
                              void* d_out, int out_size) {
    const float* x    = (const float*)d_in[0];
    const void*  ei   = d_in[1];
    const float* g1w  = (const float*)d_in[2];
    const float* g1b  = (const float*)d_in[3];
    const float* g2w  = (const float*)d_in[4];
    const float* g2b  = (const float*)d_in[5];
    const float* wih  = (const float*)d_in[6];
    const float* whh  = (const float*)d_in[7];
    const float* bih  = (const float*)d_in[8];
    const float* bhh  = (const float*)d_in[9];
    const float* dw1  = (const float*)d_in[10];
    const float* db1  = (const float*)d_in[11];
    const float* dw2  = (const float*)d_in[12];
    const float* db2  = (const float*)d_in[13];
    float* out = (float*)d_out;
    int E = in_sizes[1] / 2;

    const int SMEM = 2 * 9472 * 4;   /* 75776 bytes */
    cudaFuncSetAttribute(k_gemm_pipe<0>, cudaFuncAttributeMaxDynamicSharedMemorySize, SMEM);
    cudaFuncSetAttribute(k_gemm_pipe<1>, cudaFuncAttributeMaxDynamicSharedMemorySize, SMEM);

    /* graph preprocessing */
    k_detect<<<1, 256>>>((const int*)ei);
    k_zero_cnt<<<(NN + 255) / 256, 256>>>();
    k_count<<<(E + 255) / 256, 256>>>(ei, E);
    k_scan<<<1, 1024>>>();
    k_fill<<<(E + 255) / 256, 256>>>(ei, E);

    /* GCN1 */
    k_aggx<<<(NBW * NN * NF + 255) / 256, 256>>>(x);
    k_gcn1<<<(NBW * NN * NH + 255) / 256, 256>>>(g1w, g1b);

    /* GCN2 */
    k_gather64<<<NBW * NN, 64>>>();
    k_prep_g2w<<<(64 * NH + 255) / 256, 256>>>(g2w);
    k_gemm_pipe<0><<<dim3(1, (NBW * NN) / 128), 256, SMEM>>>(0, g2b);

    /* LSTM (pointwise fused into GEMM epilogue) */
    k_prep_lstm<<<(128 * 512 + 255) / 256, 256>>>(wih, whh);
    k_bsum<<<2, 256>>>(bih, bhh);
    k_zero_hc<<<(NBN * NH + 255) / 256, 256>>>();
    for (int t = 0; t < NW; t++) {
        k_gemm_pipe<1><<<dim3(4, (NBN + 127) / 128), 256, SMEM>>>(t, (const float*)0);
    }

    /* decoder */
    k_dec<<<NBN, 64>>>(dw1, db1, dw2, db2, out);
}

// round 9
// speedup vs baseline: 3.7699x; 1.4615x over previous
#include <cuda_runtime.h>
#include <math.h>
#include <stdint.h>

#define NB 2
#define NW 8
#define NN 10000
#define NF 5
#define NH 128
#define NBW 16          /* NB*NW */
#define NBN 20000       /* NB*NN */
#define NE_MAX 80000

/* ---------------- scratch (device globals; no allocations allowed) -------- */
__device__ int   d_is64;
__device__ float d_dinv[NN];
__device__ int   d_cnt[NN];
__device__ int   d_rowptr[NN + 1];
__device__ int   d_cursor[NN];
__device__ int   d_colsrc[NE_MAX];
__device__ float d_xagg[NBW * NN * NF];
__device__ float d_h1[NBW * NN * NH];
/* fp16 planes, k-pairs packed in u32 (elem 2j low half, 2j+1 high) */
__device__ uint32_t d_h1p[NBW * NN * 64];   /* gathered layer-2 input */
__device__ uint32_t d_h2p[NBW * NN * 64];   /* gcn2 output (lstm input) */
__device__ uint32_t d_hbp[NBN * 64];        /* lstm hidden */
__device__ uint32_t d_g2p[64 * NH];         /* gcn2 weight [k2][n] */
__device__ uint32_t d_btp[128 * 512];       /* lstm BT [k2][col'], col'=h*4+gate */
__device__ float d_bsum[512];               /* gate-interleaved bias */
__device__ float d_hbuf[NBN * NH];
__device__ float d_cbuf[NBN * NH];

__device__ __forceinline__ float sigf(float x) { return 1.0f / (1.0f + __expf(-x)); }

/* pack (x0,x1) into one f16x2 (x0 -> low half) */
__device__ __forceinline__ uint32_t pack16(float x0, float x1) {
    uint32_t h;
    asm("cvt.rn.f16x2.f32 %0, %1, %2;" : "=r"(h) : "f"(x1), "f"(x0));
    return h;
}

__device__ __forceinline__ void cpa16(uint32_t saddr, const void* g) {
    asm volatile("cp.async.cg.shared.global [%0], [%1], 16;\n" :: "r"(saddr), "l"(g));
}

/* edge_index may be int32 or int64. Dispatch via device flag set by k_detect. */
__device__ __forceinline__ int edge_at(const void* ei, int E, int which, int e) {
    if (d_is64) return (int)((const long long*)ei)[(size_t)which * E + e];
    return ((const int*)ei)[(size_t)which * E + e];
}

__global__ void k_detect(const int* __restrict__ ei32) {
    int t = threadIdx.x;
    int nz = 0;
    for (int i = 2 * t + 1; i < 4096; i += 512) nz |= ei32[i];
    __shared__ int s;
    if (t == 0) s = 0;
    __syncthreads();
    if (nz) atomicOr(&s, 1);
    __syncthreads();
    if (t == 0) d_is64 = s ? 0 : 1;
}

/* ---------------- graph preprocessing ------------------------------------ */
__global__ void k_zero_cnt() {
    int i = blockIdx.x * blockDim.x + threadIdx.x;
    if (i < NN) d_cnt[i] = 0;
}

__global__ void k_count(const void* __restrict__ ei, int E) {
    int e = blockIdx.x * blockDim.x + threadIdx.x;
    if (e < E) {
        int dst = edge_at(ei, E, 1, e);
        if (dst >= 0 && dst < NN) atomicAdd(&d_cnt[dst], 1);
    }
}

__global__ void k_scan() {
    __shared__ int ssum[1024];
    const int IPT = 10;
    int t = threadIdx.x;
    int base = t * IPT;
    int s = 0;
    for (int j = 0; j < IPT; j++) {
        int idx = base + j;
        if (idx < NN) s += d_cnt[idx];
    }
    ssum[t] = s;
    __syncthreads();
    for (int off = 1; off < 1024; off <<= 1) {
        int v = (t >= off) ? ssum[t - off] : 0;
        __syncthreads();
        ssum[t] += v;
        __syncthreads();
    }
    int run = (t == 0) ? 0 : ssum[t - 1];
    for (int j = 0; j < IPT; j++) {
        int idx = base + j;
        if (idx < NN) {
            d_rowptr[idx] = run;
            d_cursor[idx] = run;
            int c = d_cnt[idx];
            d_dinv[idx] = rsqrtf((float)(c + 1));
            run += c;
        }
    }
    if (t == 0) d_rowptr[NN] = ssum[1023];
}

__global__ void k_fill(const void* __restrict__ ei, int E) {
    int e = blockIdx.x * blockDim.x + threadIdx.x;
    if (e < E) {
        int dst = edge_at(ei, E, 1, e);
        int src = edge_at(ei, E, 0, e);
        if (dst >= 0 && dst < NN && src >= 0 && src < NN) {
            int pos = atomicAdd(&d_cursor[dst], 1);
            d_colsrc[pos] = src;
        }
    }
}

/* ---------------- GCN1: aggregate x (F=5), then x@W1 + b, relu ----------- */
__global__ void k_aggx(const float* __restrict__ x) {
    int idx = blockIdx.x * blockDim.x + threadIdx.x;
    if (idx >= NBW * NN * NF) return;
    int f = idx % NF;
    int r = idx / NF;
    int n = r % NN;
    int bw = r / NN;
    float di = d_dinv[n];
    float acc = x[(bw * NN + n) * NF + f] * di * di;
    int s0 = d_rowptr[n], s1 = d_rowptr[n + 1];
    for (int e = s0; e < s1; e++) {
        int s = d_colsrc[e];
        acc += x[(bw * NN + s) * NF + f] * d_dinv[s] * di;
    }
    d_xagg[idx] = acc;
}

__global__ void k_gcn1(const float* __restrict__ w1, const float* __restrict__ b1) {
    int idx = blockIdx.x * blockDim.x + threadIdx.x;
    if (idx >= NBW * NN * NH) return;
    int h = idx % NH;
    int r = idx / NH;
    const float* xr = &d_xagg[r * NF];
    float acc = b1[h];
#pragma unroll
    for (int f = 0; f < NF; f++) acc = fmaf(xr[f], w1[f * NH + h], acc);
    d_h1[idx] = fmaxf(acc, 0.0f);
}

/* ---------------- GCN2 aggregation -> fp16 plane -------------------------- */
__global__ void k_gather64() {
    int r = blockIdx.x;          /* bw*NN + n */
    int j = threadIdx.x;         /* 0..63 feature pair */
    int n = r % NN;
    int bwBase = r - n;
    float di = d_dinv[n];
    float2 acc = *(const float2*)&d_h1[(size_t)r * NH + 2 * j];
    acc.x *= di * di; acc.y *= di * di;
    int s0 = d_rowptr[n], s1 = d_rowptr[n + 1];
    for (int e = s0; e < s1; e++) {
        int s = __ldg(&d_colsrc[e]);
        float w = __ldg(&d_dinv[s]) * di;
        float2 v = *(const float2*)&d_h1[(size_t)(bwBase + s) * NH + 2 * j];
        acc.x = fmaf(v.x, w, acc.x);
        acc.y = fmaf(v.y, w, acc.y);
    }
    d_h1p[(size_t)r * 64 + j] = pack16(acc.x, acc.y);
}

/* ---------------- weight plane prep -------------------------------------- */
__global__ void k_prep_g2w(const float* __restrict__ g2w) {
    int idx = blockIdx.x * blockDim.x + threadIdx.x;
    if (idx >= 64 * NH) return;
    int k2 = idx >> 7, n = idx & 127;
    d_g2p[idx] = pack16(g2w[(2 * k2) * NH + n], g2w[(2 * k2 + 1) * NH + n]);
}

/* gate-interleaved: col' = h*4 + gate; original row j = gate*128 + h */
__global__ void k_prep_lstm(const float* __restrict__ wih, const float* __restrict__ whh) {
    int idx = blockIdx.x * blockDim.x + threadIdx.x;
    if (idx >= 128 * 512) return;
    int k2 = idx >> 9, col = idx & 511;
    int j = (col & 3) * 128 + (col >> 2);
    float a, b;
    if (k2 < 64) { a = wih[j * 128 + 2 * k2]; b = wih[j * 128 + 2 * k2 + 1]; }
    else         { a = whh[j * 128 + 2 * (k2 - 64)]; b = whh[j * 128 + 2 * (k2 - 64) + 1]; }
    d_btp[idx] = pack16(a, b);
}

__global__ void k_bsum(const float* __restrict__ bih, const float* __restrict__ bhh) {
    int col = blockIdx.x * blockDim.x + threadIdx.x;
    if (col < 512) {
        int j = (col & 3) * 128 + (col >> 2);
        d_bsum[col] = bih[j] + bhh[j];
    }
}

__global__ void k_zero_hc() {
    int i = blockIdx.x * blockDim.x + threadIdx.x;
    if (i < NBN * NH) { d_hbuf[i] = 0.0f; d_cbuf[i] = 0.0f; }
    if (i < NBN * 64) { d_hbp[i] = 0u; }
}

/* ---------------- pipelined fp16 tensor-core GEMM ------------------------
   MODE 0: h2 plane = relu(h1 plane(160000x128) @ g2 plane + g2b)
   MODE 1: gates = [h2_t | hbuf](20000x256) @ bt plane + bsum, full LSTM
           cell update fused in the epilogue (gate-interleaved weights).
   256 thr (8 warps 4m x 2n), block tile 128x128, warp tile 32x64, BK=32,
   cp.async double-buffered, single fp16 operands, fp32 accumulate.
---------------------------------------------------------------------------- */
template<int MODE>
__global__ __launch_bounds__(256)
void k_gemm_pipe(int t, const float* __restrict__ biasext) {
    const int M = MODE ? NBN : (NBW * NN);
    const int N = MODE ? 512 : NH;
    const int NIT = MODE ? 8 : 4;

    extern __shared__ uint32_t sm[];
    /* per buffer (u32): A 2560 | B 2176 = 4736; two buffers. */

    int tid = threadIdx.x;
    int lane = tid & 31, wid = tid >> 5;
    int wm = wid & 3, wn = wid >> 2;
    int g = lane >> 2, tq = lane & 3;
    int m0 = blockIdx.y * 128, n0 = blockIdx.x * 128;

    float c[2][8][4];
#pragma unroll
    for (int i = 0; i < 2; i++)
#pragma unroll
        for (int j = 0; j < 8; j++)
#pragma unroll
            for (int q = 0; q < 4; q++) c[i][j][q] = 0.0f;

    int arow = tid >> 1, half = tid & 1;
    int am = m0 + arow;
    int amc = am < M ? am : M - 1;
    const uint32_t *A0, *A1 = 0;
    if (MODE) {
        int b = amc / NN, n = amc - b * NN;
        A0 = d_h2p + ((size_t)(b * NW + t) * NN + n) * 64;
        A1 = d_hbp + (size_t)amc * 64;
    } else {
        A0 = d_h1p + (size_t)amc * 64;
    }
    const uint32_t* Bp = MODE ? d_btp : d_g2p;
    int bk2 = tid >> 4, nb = (tid & 15) * 8;

    uint32_t smbase = (uint32_t)__cvta_generic_to_shared(sm);
    uint32_t sAoff = (arow * 20 + half * 8) * 4;
    uint32_t sBoff = (2560 + bk2 * 136 + nb) * 4;

    auto stage = [&](int buf, int iter) {
        uint32_t sb = smbase + (uint32_t)buf * 4736 * 4;
        int k2b = iter * 16;
        const uint32_t* a = (MODE && iter >= 4) ? (A1 + (k2b - 64) + half * 8)
                                                : (A0 + k2b + half * 8);
        uint32_t sA = sb + sAoff;
        cpa16(sA, a);
        cpa16(sA + 16, a + 4);
        const uint32_t* bsrc = Bp + (size_t)(k2b + bk2) * N + n0 + nb;
        uint32_t sB = sb + sBoff;
        cpa16(sB, bsrc);
        cpa16(sB + 16, bsrc + 4);
        asm volatile("cp.async.commit_group;\n");
    };

    stage(0, 0);
    for (int iter = 0; iter < NIT; iter++) {
        int buf = iter & 1;
        if (iter + 1 < NIT) {
            stage(buf ^ 1, iter + 1);
            asm volatile("cp.async.wait_group 1;\n");
        } else {
            asm volatile("cp.async.wait_group 0;\n");
        }
        __syncthreads();

        const uint32_t* sA = sm + buf * 4736;
        const uint32_t* sB = sA + 2560;

#pragma unroll
        for (int s = 0; s < 2; s++) {
            uint32_t a[2][4], b[8][2];
            int kb = s * 8 + tq;
#pragma unroll
            for (int mt = 0; mt < 2; mt++) {
                int r = wm * 32 + mt * 16 + g;
                a[mt][0] = sA[r * 20 + kb];
                a[mt][1] = sA[(r + 8) * 20 + kb];
                a[mt][2] = sA[r * 20 + kb + 4];
                a[mt][3] = sA[(r + 8) * 20 + kb + 4];
            }
#pragma unroll
            for (int nt = 0; nt < 8; nt++) {
                int col = wn * 64 + nt * 8 + g;
                b[nt][0] = sB[kb * 136 + col];
                b[nt][1] = sB[(kb + 4) * 136 + col];
            }
#pragma unroll
            for (int mt = 0; mt < 2; mt++)
#pragma unroll
                for (int nt = 0; nt < 8; nt++) {
                    asm volatile(
                        "mma.sync.aligned.m16n8k16.row.col.f32.f16.f16.f32 "
                        "{%0,%1,%2,%3}, {%4,%5,%6,%7}, {%8,%9}, {%0,%1,%2,%3};\n"
                        : "+f"(c[mt][nt][0]), "+f"(c[mt][nt][1]),
                          "+f"(c[mt][nt][2]), "+f"(c[mt][nt][3])
                        : "r"(a[mt][0]), "r"(a[mt][1]), "r"(a[mt][2]), "r"(a[mt][3]),
                          "r"(b[nt][0]), "r"(b[nt][1]));
                }
        }
        __syncthreads();
    }

    if (MODE) {
        /* ---- fused LSTM cell epilogue (reuse pipeline smem) ---- */
        float* sf = (float*)sm;   /* [128 rows][132 cols] fp32 gates */
#pragma unroll
        for (int mt = 0; mt < 2; mt++) {
            int lr = wm * 32 + mt * 16 + g;
#pragma unroll
            for (int nt = 0; nt < 8; nt++) {
                int lc = wn * 64 + nt * 8 + tq * 2;
                float bb0 = d_bsum[n0 + lc], bb1 = d_bsum[n0 + lc + 1];
                *(float2*)&sf[lr * 132 + lc] =
                    make_float2(c[mt][nt][0] + bb0, c[mt][nt][1] + bb1);
                *(float2*)&sf[(lr + 8) * 132 + lc] =
                    make_float2(c[mt][nt][2] + bb0, c[mt][nt][3] + bb1);
            }
        }
        __syncthreads();
        int h0 = blockIdx.x * 32;   /* n0 = 4*h0 */
#pragma unroll
        for (int it = 0; it < 8; it++) {
            int idx = tid + it * 256;      /* 0..2047 */
            int lr = idx >> 4;             /* row 0..127 */
            int hp2 = idx & 15;            /* local h-pair 0..15 */
            int gm = m0 + lr;
            if (gm < M) {
                float4 gA = *(float4*)&sf[lr * 132 + hp2 * 8];      /* i,f,g,o h even */
                float4 gB = *(float4*)&sf[lr * 132 + hp2 * 8 + 4];  /* i,f,g,o h odd */
                int hg = h0 + 2 * hp2;
                int ci = gm * NH + hg;
                float2 cp = *(float2*)&d_cbuf[ci];
                float c0n = sigf(gA.y) * cp.x + sigf(gA.x) * tanhf(gA.z);
                float c1n = sigf(gB.y) * cp.y + sigf(gB.x) * tanhf(gB.z);
                float h0n = sigf(gA.w) * tanhf(c0n);
                float h1n = sigf(gB.w) * tanhf(c1n);
                *(float2*)&d_cbuf[ci] = make_float2(c0n, c1n);
                *(float2*)&d_hbuf[ci] = make_float2(h0n, h1n);
                d_hbp[(size_t)gm * 64 + (hg >> 1)] = pack16(h0n, h1n);
            }
        }
    } else {
        /* ---- GCN2 epilogue: relu + pack to h2 plane ---- */
#pragma unroll
        for (int mt = 0; mt < 2; mt++) {
            int r0 = m0 + wm * 32 + mt * 16 + g;
#pragma unroll
            for (int nt = 0; nt < 8; nt++) {
                int col = n0 + wn * 64 + nt * 8 + tq * 2;
                float bb0 = biasext[col], bb1 = biasext[col + 1];
                if (r0 < M) {
                    float v0 = fmaxf(c[mt][nt][0] + bb0, 0.f);
                    float v1 = fmaxf(c[mt][nt][1] + bb1, 0.f);
                    d_h2p[(size_t)r0 * 64 + (col >> 1)] = pack16(v0, v1);
                }
                if (r0 + 8 < M) {
                    float v2 = fmaxf(c[mt][nt][2] + bb0, 0.f);
                    float v3 = fmaxf(c[mt][nt][3] + bb1, 0.f);
                    d_h2p[(size_t)(r0 + 8) * 64 + (col >> 1)] = pack16(v2, v3);
                }
            }
        }
    }
}

/* ---------------- decoder: relu(h@W1+b1) @ W2 + b2 ----------------------- */
__global__ void k_dec(const float* __restrict__ w1, const float* __restrict__ b1,
                      const float* __restrict__ w2, const float* __restrict__ b2,
                      float* __restrict__ out) {
    int m = blockIdx.x;
    int j = threadIdx.x;
    const float* hr = &d_hbuf[m * NH];
    float acc = b1[j];
#pragma unroll 8
    for (int k = 0; k < NH; k++) acc = fmaf(hr[k], w1[k * 64 + j], acc);
    __shared__ float red[64];
    red[j] = fmaxf(acc, 0.0f) * w2[j];
    __syncthreads();
    for (int off = 32; off > 0; off >>= 1) {
        if (j < off) red[j] += red[j + off];
        __syncthreads();
    }
    if (j == 0) out[m] = red[0] + b2[0];
}

/* ---------------- host entry --------------------------------------------- */
extern "C" void kernel_launch(void* const* d_in, const int* in_sizes, int n_in,
                              void* d_out, int out_size) {
    const float* x    = (const float*)d_in[0];
    const void*  ei   = d_in[1];
    const float* g1w  = (const float*)d_in[2];
    const float* g1b  = (const float*)d_in[3];
    const float* g2w  = (const float*)d_in[4];
    const float* g2b  = (const float*)d_in[5];
    const float* wih  = (const float*)d_in[6];
    const float* whh  = (const float*)d_in[7];
    const float* bih  = (const float*)d_in[8];
    const float* bhh  = (const float*)d_in[9];
    const float* dw1  = (const float*)d_in[10];
    const float* db1  = (const float*)d_in[11];
    const float* dw2  = (const float*)d_in[12];
    const float* db2  = (const float*)d_in[13];
    float* out = (float*)d_out;
    int E = in_sizes[1] / 2;

    /* pipeline needs 2*4736*4 = 37888; MODE1 epilogue needs 128*132*4 = 67584 */
    const int SMEM = 128 * 132 * 4;
    cudaFuncSetAttribute(k_gemm_pipe<0>, cudaFuncAttributeMaxDynamicSharedMemorySize, SMEM);
    cudaFuncSetAttribute(k_gemm_pipe<1>, cudaFuncAttributeMaxDynamicSharedMemorySize, SMEM);

    /* graph preprocessing */
    k_detect<<<1, 256>>>((const int*)ei);
    k_zero_cnt<<<(NN + 255) / 256, 256>>>();
    k_count<<<(E + 255) / 256, 256>>>(ei, E);
    k_scan<<<1, 1024>>>();
    k_fill<<<(E + 255) / 256, 256>>>(ei, E);

    /* GCN1 */
    k_aggx<<<(NBW * NN * NF + 255) / 256, 256>>>(x);
    k_gcn1<<<(NBW * NN * NH + 255) / 256, 256>>>(g1w, g1b);

    /* GCN2 */
    k_gather64<<<NBW * NN, 64>>>();
    k_prep_g2w<<<(64 * NH + 255) / 256, 256>>>(g2w);
    k_gemm_pipe<0><<<dim3(1, (NBW * NN) / 128), 256, SMEM>>>(0, g2b);

    /* LSTM (cell update fused into GEMM epilogue) */
    k_prep_lstm<<<(128 * 512 + 255) / 256, 256>>>(wih, whh);
    k_bsum<<<2, 256>>>(bih, bhh);
    k_zero_hc<<<(NBN * NH + 255) / 256, 256>>>();
    for (int t = 0; t < NW; t++) {
        k_gemm_pipe<1><<<dim3(4, (NBN + 127) / 128), 256, SMEM>>>(t, (const float*)0);
    }

    /* decoder */
    k_dec<<<NBN, 64>>>(dw1, db1, dw2, db2, out);
}